// round 14
// baseline (speedup 1.0000x reference)
#include <cuda_runtime.h>
#include <cuda_bf16.h>
#include <math.h>
#include <stdint.h>

#define DMODEL 768
#define FFD    3072
#define NL     6
#define NH     12
#define DH     64
#define SEQ    512
#define BATCH  8
#define NTOK   (BATCH*SEQ)   // 4096

#define SZ_DD  (NL*DMODEL*DMODEL)
#define SZ_DF  (NL*DMODEL*FFD)
#define OQ 0
#define OKk (SZ_DD)
#define OV  (2*SZ_DD)
#define OO  (3*SZ_DD)
#define O1  (4*SZ_DD)
#define O2  (4*SZ_DD + SZ_DF)
#define WTOT (4*SZ_DD + 2*SZ_DF)

// ---------------- scratch (static device globals; no runtime allocation) ----
__device__ float g_h  [NTOK*DMODEL];
__device__ float g_h2 [NTOK*DMODEL];
__device__ float g_tmp[NTOK*DMODEL];
__device__ __nv_bfloat16 g_whi[WTOT];
__device__ __nv_bfloat16 g_wlo[WTOT];
__device__ __nv_bfloat16 g_ahi[NTOK*DMODEL];
__device__ __nv_bfloat16 g_alo[NTOK*DMODEL];
__device__ __nv_bfloat16 g_qhi[NTOK*DMODEL];
__device__ __nv_bfloat16 g_qlo[NTOK*DMODEL];
__device__ __nv_bfloat16 g_khi[NTOK*DMODEL];
__device__ __nv_bfloat16 g_klo[NTOK*DMODEL];
__device__ __nv_bfloat16 g_vhi[NTOK*DMODEL];
__device__ __nv_bfloat16 g_vlo[NTOK*DMODEL];
__device__ __nv_bfloat16 g_chi[NTOK*DMODEL];
__device__ __nv_bfloat16 g_clo[NTOK*DMODEL];
__device__ __nv_bfloat16 g_fhi[NTOK*FFD];
__device__ __nv_bfloat16 g_flo[NTOK*FFD];

// ================= helpers ==================================================
__device__ __forceinline__ uint32_t smem_u32(const void* p) {
    uint32_t a;
    asm("{ .reg .u64 t; cvta.to.shared.u64 t, %1; cvt.u32.u64 %0, t; }"
        : "=r"(a) : "l"(p));
    return a;
}
__device__ __forceinline__ uint32_t packbf(float x, float y) {
    __nv_bfloat162 t = __floats2bfloat162_rn(x, y);
    return *(uint32_t*)&t;
}
__device__ __forceinline__ void cpa16(uint32_t dst, const void* src) {
    asm volatile("cp.async.cg.shared.global [%0], [%1], 16;"
                 :: "r"(dst), "l"(src) : "memory");
}
__device__ __forceinline__ void ldsm4(uint32_t* r, uint32_t addr) {
    asm volatile("ldmatrix.sync.aligned.m8n8.x4.shared.b16 {%0,%1,%2,%3}, [%4];"
                 : "=r"(r[0]), "=r"(r[1]), "=r"(r[2]), "=r"(r[3]) : "r"(addr));
}
__device__ __forceinline__ void ldsm4t(uint32_t* r, uint32_t addr) {
    asm volatile("ldmatrix.sync.aligned.m8n8.x4.trans.shared.b16 {%0,%1,%2,%3}, [%4];"
                 : "=r"(r[0]), "=r"(r[1]), "=r"(r[2]), "=r"(r[3]) : "r"(addr));
}
__device__ __forceinline__ void mma16816(float* d, const uint32_t* a,
                                         uint32_t b0, uint32_t b1) {
    asm volatile(
        "mma.sync.aligned.m16n8k16.row.col.f32.bf16.bf16.f32 "
        "{%0,%1,%2,%3}, {%4,%5,%6,%7}, {%8,%9}, {%0,%1,%2,%3};"
        : "+f"(d[0]), "+f"(d[1]), "+f"(d[2]), "+f"(d[3])
        : "r"(a[0]), "r"(a[1]), "r"(a[2]), "r"(a[3]), "r"(b0), "r"(b1));
}

// ================= fp32 -> bf16 hi/lo split conversion ======================
__global__ __launch_bounds__(256)
void f2bf(const float4* __restrict__ in, uint2* __restrict__ hi,
          uint2* __restrict__ lo, int n4)
{
    int i = blockIdx.x * 256 + threadIdx.x;
    if (i >= n4) return;
    float4 f = in[i];
    float hx = __bfloat162float(__float2bfloat16_rn(f.x));
    float hy = __bfloat162float(__float2bfloat16_rn(f.y));
    float hz = __bfloat162float(__float2bfloat16_rn(f.z));
    float hw = __bfloat162float(__float2bfloat16_rn(f.w));
    uint2 H = { packbf(hx, hy), packbf(hz, hw) };
    uint2 Lo = { packbf(f.x - hx, f.y - hy), packbf(f.z - hz, f.w - hw) };
    hi[i] = H;
    lo[i] = Lo;
}

struct F2Job { const float4* in; uint2* hi; uint2* lo; int n4; };
struct F2Params4 { F2Job j[4]; };
__global__ __launch_bounds__(256)
void f2bf_multi4(F2Params4 P)
{
    const F2Job& J = P.j[blockIdx.y];
    int i = blockIdx.x * 256 + threadIdx.x;
    if (i >= J.n4) return;
    float4 f = J.in[i];
    float hx = __bfloat162float(__float2bfloat16_rn(f.x));
    float hy = __bfloat162float(__float2bfloat16_rn(f.y));
    float hz = __bfloat162float(__float2bfloat16_rn(f.z));
    float hw = __bfloat162float(__float2bfloat16_rn(f.w));
    uint2 H = { packbf(hx, hy), packbf(hz, hw) };
    uint2 Lo = { packbf(f.x - hx, f.y - hy), packbf(f.z - hz, f.w - hw) };
    J.hi[i] = H;
    J.lo[i] = Lo;
}
struct F2Params2 { F2Job j[2]; };
__global__ __launch_bounds__(256)
void f2bf_multi2(F2Params2 P)
{
    const F2Job& J = P.j[blockIdx.y];
    int i = blockIdx.x * 256 + threadIdx.x;
    if (i >= J.n4) return;
    float4 f = J.in[i];
    float hx = __bfloat162float(__float2bfloat16_rn(f.x));
    float hy = __bfloat162float(__float2bfloat16_rn(f.y));
    float hz = __bfloat162float(__float2bfloat16_rn(f.z));
    float hw = __bfloat162float(__float2bfloat16_rn(f.w));
    uint2 H = { packbf(hx, hy), packbf(hz, hw) };
    uint2 Lo = { packbf(f.x - hx, f.y - hy), packbf(f.z - hz, f.w - hw) };
    J.hi[i] = H;
    J.lo[i] = Lo;
}

// ================= split-bf16 HMMA GEMM (templated M-tile) ==================
struct GemmJob {
    const __nv_bfloat16 *Bh, *Bl;
    const float* bias;
    float* C;
    __nv_bfloat16 *Chi, *Clo;
    float scale;
    int act;
};
struct GemmParams { GemmJob job[3]; };

template <int MT>
__global__ __launch_bounds__(128, (MT == 2) ? 3 : 2)
void hmma_gemm(const __nv_bfloat16* __restrict__ Ahi,
               const __nv_bfloat16* __restrict__ Alo,
               GemmParams P, int M, int N, int K)
{
    constexpr int ASEC = MT * 2560;
    constexpr int BOFF = 2 * ASEC;
    constexpr int STG  = 2 * ASEC + 16384;
    constexpr int CTAM = MT * 32;

    extern __shared__ char dsm[];
    const GemmJob& J = P.job[blockIdx.z];
    const __nv_bfloat16* __restrict__ Bhi = J.Bh;
    const __nv_bfloat16* __restrict__ Blo = J.Bl;

    const uint32_t sb = smem_u32(dsm);
    const int tid = threadIdx.x;
    const int wid = tid >> 5, L = tid & 31;
    const int wm = wid & 1, wn = wid >> 1;
    const int row0 = blockIdx.y * CTAM, col0 = blockIdx.x * 128;

    float acc[MT][8][4];
    #pragma unroll
    for (int i = 0; i < MT; i++)
        #pragma unroll
        for (int j = 0; j < 8; j++)
            #pragma unroll
            for (int t = 0; t < 4; t++) acc[i][j][t] = 0.f;

    const int aR = tid >> 2, aU = tid & 3;
    const int bR = tid >> 4, bU = tid & 15;
    const uint32_t aDst = (uint32_t)(aR * 80 + aU * 16);
    const uint32_t bDst = (uint32_t)(bR * 256 + ((bU ^ (bR & 7)) << 4));

    const __nv_bfloat16* aHb = Ahi + (size_t)(row0 + aR) * K + aU * 8;
    const __nv_bfloat16* aLb = Alo + (size_t)(row0 + aR) * K + aU * 8;
    const __nv_bfloat16* bHb = Bhi + (size_t)bR * N + col0 + bU * 8;
    const __nv_bfloat16* bLb = Blo + (size_t)bR * N + col0 + bU * 8;

    const int KB = K >> 5;

    #define ISSUE(kb) do {                                                    \
        const uint32_t stg_ = sb + (uint32_t)((kb) & 1) * STG;                \
        const int k0_ = (kb) * 32;                                            \
        _Pragma("unroll")                                                     \
        for (int p = 0; p < MT; p++) {                                        \
            cpa16(stg_ + aDst + p * 2560,        aHb + k0_ + (size_t)(p*32) * K); \
            cpa16(stg_ + ASEC + aDst + p * 2560, aLb + k0_ + (size_t)(p*32) * K); \
        }                                                                     \
        _Pragma("unroll")                                                     \
        for (int p = 0; p < 4; p++) {                                         \
            cpa16(stg_ + BOFF + bDst + p * 2048,        bHb + (size_t)(k0_ + p*8) * N); \
            cpa16(stg_ + BOFF + 8192 + bDst + p * 2048, bLb + (size_t)(k0_ + p*8) * N); \
        }                                                                     \
        asm volatile("cp.async.commit_group;" ::: "memory");                  \
    } while (0)

    ISSUE(0);

    const uint32_t aLane = (uint32_t)((wm * (MT*16) + (L & 15)) * 80 + ((L >> 4) << 4));
    const uint32_t bRow  = (uint32_t)(L & 15);
    const uint32_t bSwzX = (uint32_t)(L & 7);
    const uint32_t bUL   = (uint32_t)(wn * 8 + (L >> 4));

    for (int kb = 0; kb < KB; kb++) {
        const uint32_t stg = sb + (uint32_t)(kb & 1) * STG;
        asm volatile("cp.async.wait_group 0;" ::: "memory");
        __syncthreads();
        if (kb + 1 < KB) ISSUE(kb + 1);

        #pragma unroll
        for (int ks = 0; ks < 2; ks++) {
            uint32_t ah[MT][4], al[MT][4];
            #pragma unroll
            for (int mt = 0; mt < MT; mt++) {
                uint32_t off = aLane + (uint32_t)(mt * 16 * 80 + ks * 32);
                ldsm4(ah[mt], stg + off);
                ldsm4(al[mt], stg + ASEC + off);
            }
            #pragma unroll
            for (int nj = 0; nj < 8; nj += 2) {
                uint32_t bh[4], bl[4];
                uint32_t off = (uint32_t)(ks * 16 + bRow) * 256
                             + (((bUL + nj) ^ bSwzX) << 4);
                ldsm4t(bh, stg + BOFF + off);
                ldsm4t(bl, stg + BOFF + 8192 + off);
                #pragma unroll
                for (int mt = 0; mt < MT; mt++) {
                    mma16816(acc[mt][nj],   ah[mt], bh[0], bh[1]);
                    mma16816(acc[mt][nj+1], ah[mt], bh[2], bh[3]);
                    mma16816(acc[mt][nj],   ah[mt], bl[0], bl[1]);
                    mma16816(acc[mt][nj+1], ah[mt], bl[2], bl[3]);
                    mma16816(acc[mt][nj],   al[mt], bh[0], bh[1]);
                    mma16816(acc[mt][nj+1], al[mt], bh[2], bh[3]);
                }
            }
        }
        __syncthreads();
    }
    #undef ISSUE

    // ---- single-pass epilogue ----------------------------------------------
    const float* bias = J.bias;
    float* C = J.C;
    __nv_bfloat16 *Chi = J.Chi, *Clo = J.Clo;
    const float scale = J.scale;
    const int act = J.act;

    float* sOut = (float*)dsm;               // CTAM x 132 fp32
    const int gid = L >> 2, tig = L & 3;
    #pragma unroll
    for (int mt = 0; mt < MT; mt++) {
        #pragma unroll
        for (int nt = 0; nt < 8; nt++) {
            const int srow = wm * (MT*16) + mt * 16 + gid;
            const int scol = wn * 64 + nt * 8 + tig * 2;
            const int gc   = col0 + scol;
            float b0v = bias[gc], b1v = bias[gc + 1];
            float v0 = (acc[mt][nt][0] + b0v) * scale;
            float v1 = (acc[mt][nt][1] + b1v) * scale;
            float v2 = (acc[mt][nt][2] + b0v) * scale;
            float v3 = (acc[mt][nt][3] + b1v) * scale;
            if (act) {
                v0 = 0.5f*v0*(1.f+erff(v0*0.70710678118654752f));
                v1 = 0.5f*v1*(1.f+erff(v1*0.70710678118654752f));
                v2 = 0.5f*v2*(1.f+erff(v2*0.70710678118654752f));
                v3 = 0.5f*v3*(1.f+erff(v3*0.70710678118654752f));
            }
            sOut[srow * 132 + scol]       = v0;
            sOut[srow * 132 + scol + 1]   = v1;
            sOut[(srow+8) * 132 + scol]   = v2;
            sOut[(srow+8) * 132 + scol+1] = v3;
        }
    }
    __syncthreads();
    #pragma unroll
    for (int i = 0; i < MT*8; i++) {
        const int f   = tid + i * 128;
        const int row = f >> 5;
        const int c4  = (f & 31) * 4;
        float4 v = *(const float4*)(sOut + row * 132 + c4);
        const size_t gidx = (size_t)(row0 + row) * N + col0 + c4;
        if (C) *(float4*)(C + gidx) = v;
        if (Chi) {
            float hx = __bfloat162float(__float2bfloat16_rn(v.x));
            float hy = __bfloat162float(__float2bfloat16_rn(v.y));
            float hz = __bfloat162float(__float2bfloat16_rn(v.z));
            float hw = __bfloat162float(__float2bfloat16_rn(v.w));
            uint2 H = { packbf(hx, hy), packbf(hz, hw) };
            uint2 Lo = { packbf(v.x - hx, v.y - hy), packbf(v.z - hz, v.w - hw) };
            *(uint2*)(Chi + gidx) = H;
            *(uint2*)(Clo + gidx) = Lo;
        }
    }
}

#define GEMM_SMEM4 (2*(4*2560*2 + 16384))   // 73728
#define GEMM_SMEM2 (2*(2*2560*2 + 16384))   // 53248

// ================= HMMA flash attention (R11 config: 49KB, occ3) ============
#define ATT_SMEM (49152 + 256)

__global__ __launch_bounds__(128, 3)
void attn_hmma(const __nv_bfloat16* __restrict__ Qh, const __nv_bfloat16* __restrict__ Ql,
               const __nv_bfloat16* __restrict__ Kh, const __nv_bfloat16* __restrict__ Kl,
               const __nv_bfloat16* __restrict__ Vh, const __nv_bfloat16* __restrict__ Vl,
               const int* __restrict__ mask,
               __nv_bfloat16* __restrict__ Ohi, __nv_bfloat16* __restrict__ Olo)
{
    extern __shared__ char sm[];
    const uint32_t sb = smem_u32(sm);
    float* msk_s = (float*)(sm + 49152);
    const int tid = threadIdx.x, w = tid >> 5, L = tid & 31;
    const int qt = blockIdx.x, hh = blockIdx.y, b = blockIdx.z;
    const size_t base = (size_t)b * SEQ * DMODEL + (size_t)hh * DH;

    {
        const __nv_bfloat16* qh = Qh + base + (size_t)(qt * 64) * DMODEL;
        const __nv_bfloat16* ql = Ql + base + (size_t)(qt * 64) * DMODEL;
        #pragma unroll
        for (int it = 0; it < 4; it++) {
            int u = tid + it * 128;
            int r = u >> 3, c = u & 7;
            uint32_t off = (uint32_t)(r * 128 + ((c ^ (r & 7)) << 4));
            *(uint4*)(sm + off)        = *(const uint4*)(qh + (size_t)r * DMODEL + c * 8);
            *(uint4*)(sm + 8192 + off) = *(const uint4*)(ql + (size_t)r * DMODEL + c * 8);
        }
    }

    float m0 = -1e30f, m1 = -1e30f, l0 = 0.f, l1 = 0.f;
    float o[8][4];
    #pragma unroll
    for (int f = 0; f < 8; f++)
        #pragma unroll
        for (int t = 0; t < 4; t++) o[f][t] = 0.f;

    for (int kt = 0; kt < SEQ / 64; kt++) {
        __syncthreads();
        {
            const size_t kb = base + (size_t)(kt * 64) * DMODEL;
            #pragma unroll
            for (int it = 0; it < 4; it++) {
                int u = tid + it * 128;
                int r = u >> 3, c = u & 7;
                uint32_t off = (uint32_t)(r * 128 + ((c ^ (r & 7)) << 4));
                size_t g = kb + (size_t)r * DMODEL + c * 8;
                *(uint4*)(sm + 16384 + off) = *(const uint4*)(Kh + g);
                *(uint4*)(sm + 24576 + off) = *(const uint4*)(Kl + g);
                *(uint4*)(sm + 32768 + off) = *(const uint4*)(Vh + g);
                *(uint4*)(sm + 40960 + off) = *(const uint4*)(Vl + g);
            }
            if (tid < 64) msk_s[tid] = (float)mask[b * SEQ + kt * 64 + tid];
        }
        __syncthreads();

        float s[8][4];
        #pragma unroll
        for (int f = 0; f < 8; f++)
            #pragma unroll
            for (int t = 0; t < 4; t++) s[f][t] = 0.f;

        #pragma unroll
        for (int ks = 0; ks < 4; ks++) {
            const int qrow = w * 16 + (L & 15);
            const uint32_t qoff = (uint32_t)(qrow * 128
                                  + (((ks * 2 + (L >> 4)) ^ (qrow & 7)) << 4));
            uint32_t qhf[4], qlf[4];
            ldsm4(qhf, sb + qoff);
            ldsm4(qlf, sb + 8192 + qoff);
            #pragma unroll
            for (int nj = 0; nj < 4; nj++) {
                const int krow = nj * 16 + (L & 7) + ((L >> 4) << 3);
                const uint32_t koff = (uint32_t)(krow * 128
                                      + (((ks * 2 + ((L >> 3) & 1)) ^ (krow & 7)) << 4));
                uint32_t khf[4], klf[4];
                ldsm4(khf, sb + 16384 + koff);
                ldsm4(klf, sb + 24576 + koff);
                mma16816(s[2*nj],   qhf, khf[0], khf[1]);
                mma16816(s[2*nj+1], qhf, khf[2], khf[3]);
                mma16816(s[2*nj],   qhf, klf[0], klf[1]);
                mma16816(s[2*nj+1], qhf, klf[2], klf[3]);
                mma16816(s[2*nj],   qlf, khf[0], khf[1]);
                mma16816(s[2*nj+1], qlf, khf[2], khf[3]);
            }
        }

        #pragma unroll
        for (int f = 0; f < 8; f++) {
            float mk0 = msk_s[f * 8 + 2 * (L & 3)];
            float mk1 = msk_s[f * 8 + 2 * (L & 3) + 1];
            if (mk0 == 0.f) { s[f][0] = -1e9f; s[f][2] = -1e9f; }
            if (mk1 == 0.f) { s[f][1] = -1e9f; s[f][3] = -1e9f; }
        }

        float mx0 = -1e30f, mx1 = -1e30f;
        #pragma unroll
        for (int f = 0; f < 8; f++) {
            mx0 = fmaxf(mx0, fmaxf(s[f][0], s[f][1]));
            mx1 = fmaxf(mx1, fmaxf(s[f][2], s[f][3]));
        }
        #pragma unroll
        for (int ofs = 1; ofs <= 2; ofs <<= 1) {
            mx0 = fmaxf(mx0, __shfl_xor_sync(0xffffffffu, mx0, ofs, 4));
            mx1 = fmaxf(mx1, __shfl_xor_sync(0xffffffffu, mx1, ofs, 4));
        }
        float mn0 = fmaxf(m0, mx0), mn1 = fmaxf(m1, mx1);
        float al0 = __expf(m0 - mn0), al1 = __expf(m1 - mn1);
        m0 = mn0; m1 = mn1;
        float sum0 = 0.f, sum1 = 0.f;
        #pragma unroll
        for (int f = 0; f < 8; f++) {
            s[f][0] = __expf(s[f][0] - mn0); sum0 += s[f][0];
            s[f][1] = __expf(s[f][1] - mn0); sum0 += s[f][1];
            s[f][2] = __expf(s[f][2] - mn1); sum1 += s[f][2];
            s[f][3] = __expf(s[f][3] - mn1); sum1 += s[f][3];
        }
        #pragma unroll
        for (int ofs = 1; ofs <= 2; ofs <<= 1) {
            sum0 += __shfl_xor_sync(0xffffffffu, sum0, ofs, 4);
            sum1 += __shfl_xor_sync(0xffffffffu, sum1, ofs, 4);
        }
        l0 = l0 * al0 + sum0;
        l1 = l1 * al1 + sum1;
        #pragma unroll
        for (int f = 0; f < 8; f++) {
            o[f][0] *= al0; o[f][1] *= al0; o[f][2] *= al1; o[f][3] *= al1;
        }

        #pragma unroll
        for (int s4 = 0; s4 < 4; s4++) {
            uint32_t ph[4], pl[4];
            {
                float p00 = s[2*s4][0],   p01 = s[2*s4][1];
                float p02 = s[2*s4][2],   p03 = s[2*s4][3];
                float p10 = s[2*s4+1][0], p11 = s[2*s4+1][1];
                float p12 = s[2*s4+1][2], p13 = s[2*s4+1][3];
                ph[0] = packbf(p00, p01); ph[1] = packbf(p02, p03);
                ph[2] = packbf(p10, p11); ph[3] = packbf(p12, p13);
                pl[0] = packbf(p00 - __bfloat162float(__float2bfloat16_rn(p00)),
                               p01 - __bfloat162float(__float2bfloat16_rn(p01)));
                pl[1] = packbf(p02 - __bfloat162float(__float2bfloat16_rn(p02)),
                               p03 - __bfloat162float(__float2bfloat16_rn(p03)));
                pl[2] = packbf(p10 - __bfloat162float(__float2bfloat16_rn(p10)),
                               p11 - __bfloat162float(__float2bfloat16_rn(p11)));
                pl[3] = packbf(p12 - __bfloat162float(__float2bfloat16_rn(p12)),
                               p13 - __bfloat162float(__float2bfloat16_rn(p13)));
            }
            #pragma unroll
            for (int dj = 0; dj < 4; dj++) {
                const int vrow = s4 * 16 + (L & 15);
                const uint32_t voff = (uint32_t)(vrow * 128
                                      + (((dj * 2 + (L >> 4)) ^ (vrow & 7)) << 4));
                uint32_t vhf[4], vlf[4];
                ldsm4t(vhf, sb + 32768 + voff);
                ldsm4t(vlf, sb + 40960 + voff);
                mma16816(o[2*dj],   ph, vhf[0], vhf[1]);
                mma16816(o[2*dj+1], ph, vhf[2], vhf[3]);
                mma16816(o[2*dj],   ph, vlf[0], vlf[1]);
                mma16816(o[2*dj+1], ph, vlf[2], vlf[3]);
                mma16816(o[2*dj],   pl, vhf[0], vhf[1]);
                mma16816(o[2*dj+1], pl, vhf[2], vhf[3]);
            }
        }
    }

    const float inv0 = 1.f / l0, inv1 = 1.f / l1;
    const int r0 = qt * 64 + w * 16 + (L >> 2);
    #pragma unroll
    for (int f = 0; f < 8; f++) {
        const int c = f * 8 + 2 * (L & 3);
        const size_t i0 = base + (size_t)r0 * DMODEL + c;
        const size_t i1 = base + (size_t)(r0 + 8) * DMODEL + c;
        float v0 = o[f][0] * inv0, v1 = o[f][1] * inv0;
        float v2 = o[f][2] * inv1, v3 = o[f][3] * inv1;
        float h0 = __bfloat162float(__float2bfloat16_rn(v0));
        float h1 = __bfloat162float(__float2bfloat16_rn(v1));
        float h2v = __bfloat162float(__float2bfloat16_rn(v2));
        float h3 = __bfloat162float(__float2bfloat16_rn(v3));
        *(uint32_t*)(Ohi + i0) = packbf(v0, v1);
        *(uint32_t*)(Olo + i0) = packbf(v0 - h0, v1 - h1);
        *(uint32_t*)(Ohi + i1) = packbf(v2, v3);
        *(uint32_t*)(Olo + i1) = packbf(v2 - h2v, v3 - h3);
    }
}

// ---------------- residual add + LayerNorm (single fused reduction) ---------
__global__ __launch_bounds__(192)
void add_ln_kernel(const float* __restrict__ a, const float* __restrict__ res,
                   const float* __restrict__ g, const float* __restrict__ bt,
                   float* __restrict__ out,
                   __nv_bfloat16* __restrict__ ohi, __nv_bfloat16* __restrict__ olo)
{
    __shared__ float red[12];
    const int row = blockIdx.x;
    const int c4 = threadIdx.x * 4;
    const int lane = threadIdx.x & 31, wid = threadIdx.x >> 5;
    const size_t rb = (size_t)row * DMODEL + c4;

    float4 av = *(const float4*)(a + rb);
    float4 rv = *(const float4*)(res + rb);
    float v0 = av.x + rv.x, v1 = av.y + rv.y, v2 = av.z + rv.z, v3 = av.w + rv.w;

    float p = v0 + v1 + v2 + v3;
    float q = v0*v0 + v1*v1 + v2*v2 + v3*v3;
    #pragma unroll
    for (int o = 16; o > 0; o >>= 1) {
        p += __shfl_down_sync(0xffffffffu, p, o);
        q += __shfl_down_sync(0xffffffffu, q, o);
    }
    if (lane == 0) { red[wid] = p; red[6 + wid] = q; }
    __syncthreads();
    if (wid == 0) {
        float pp = (lane < 6) ? red[lane] : 0.f;
        float qq = (lane < 6) ? red[6 + lane] : 0.f;
        #pragma unroll
        for (int o = 4; o > 0; o >>= 1) {
            pp += __shfl_down_sync(0xffffffffu, pp, o);
            qq += __shfl_down_sync(0xffffffffu, qq, o);
        }
        if (lane == 0) { red[0] = pp; red[1] = qq; }
    }
    __syncthreads();
    const float mu  = red[0] * (1.f / DMODEL);
    const float var = red[1] * (1.f / DMODEL) - mu * mu;
    const float rs  = rsqrtf(var + 1e-12f);

    float4 gv = *(const float4*)(g + c4);
    float4 bv = *(const float4*)(bt + c4);
    float o0 = (v0 - mu) * rs * gv.x + bv.x;
    float o1 = (v1 - mu) * rs * gv.y + bv.y;
    float o2 = (v2 - mu) * rs * gv.z + bv.z;
    float o3 = (v3 - mu) * rs * gv.w + bv.w;
    float4 ov = { o0, o1, o2, o3 };
    *(float4*)(out + rb) = ov;
    if (ohi) {
        float h0 = __bfloat162float(__float2bfloat16_rn(o0));
        float h1 = __bfloat162float(__float2bfloat16_rn(o1));
        float h2 = __bfloat162float(__float2bfloat16_rn(o2));
        float h3 = __bfloat162float(__float2bfloat16_rn(o3));
        uint2 H  = { packbf(o0, o1), packbf(o2, o3) };
        uint2 Lo = { packbf(o0 - h0, o1 - h1), packbf(o2 - h2, o3 - h3) };
        *(uint2*)(ohi + rb) = H;
        *(uint2*)(olo + rb) = Lo;
    }
}

// ---------------- driver -----------------------------------------------------
extern "C" void kernel_launch(void* const* d_in, const int* in_sizes, int n_in,
                              void* d_out, int out_size)
{
    const float* x     = (const float*)d_in[0];
    const int*   amask = (const int*)  d_in[1];
    const float* Wq    = (const float*)d_in[2];
    const float* bq    = (const float*)d_in[3];
    const float* Wk    = (const float*)d_in[4];
    const float* bk    = (const float*)d_in[5];
    const float* Wv    = (const float*)d_in[6];
    const float* bv    = (const float*)d_in[7];
    const float* Wo    = (const float*)d_in[8];
    const float* bo    = (const float*)d_in[9];
    const float* ln1g  = (const float*)d_in[10];
    const float* ln1b  = (const float*)d_in[11];
    const float* W1    = (const float*)d_in[12];
    const float* b1    = (const float*)d_in[13];
    const float* W2    = (const float*)d_in[14];
    const float* b2    = (const float*)d_in[15];
    const float* ln2g  = (const float*)d_in[16];
    const float* ln2b  = (const float*)d_in[17];
    float* out = (float*)d_out;

    float *h, *h2, *tmp;
    __nv_bfloat16 *whi, *wlo, *ahi, *alo, *chi, *clo, *fhi, *flo;
    __nv_bfloat16 *qhi, *qlo, *khi, *klo, *vhi, *vlo;
    cudaGetSymbolAddress((void**)&h,   g_h);
    cudaGetSymbolAddress((void**)&h2,  g_h2);
    cudaGetSymbolAddress((void**)&tmp, g_tmp);
    cudaGetSymbolAddress((void**)&whi, g_whi);
    cudaGetSymbolAddress((void**)&wlo, g_wlo);
    cudaGetSymbolAddress((void**)&ahi, g_ahi);
    cudaGetSymbolAddress((void**)&alo, g_alo);
    cudaGetSymbolAddress((void**)&qhi, g_qhi);
    cudaGetSymbolAddress((void**)&qlo, g_qlo);
    cudaGetSymbolAddress((void**)&khi, g_khi);
    cudaGetSymbolAddress((void**)&klo, g_klo);
    cudaGetSymbolAddress((void**)&vhi, g_vhi);
    cudaGetSymbolAddress((void**)&vlo, g_vlo);
    cudaGetSymbolAddress((void**)&chi, g_chi);
    cudaGetSymbolAddress((void**)&clo, g_clo);
    cudaGetSymbolAddress((void**)&fhi, g_fhi);
    cudaGetSymbolAddress((void**)&flo, g_flo);

    cudaFuncSetAttribute(hmma_gemm<4>, cudaFuncAttributeMaxDynamicSharedMemorySize, GEMM_SMEM4);
    cudaFuncSetAttribute(hmma_gemm<2>, cudaFuncAttributeMaxDynamicSharedMemorySize, GEMM_SMEM2);
    cudaFuncSetAttribute(attn_hmma, cudaFuncAttributeMaxDynamicSharedMemorySize, ATT_SMEM);

    const int nDD4 = SZ_DD / 4;
    const int nDF4 = SZ_DF / 4;

    F2Params4 f4 = {};
    f4.j[0] = { (const float4*)Wq, (uint2*)(whi+OQ),  (uint2*)(wlo+OQ),  nDD4 };
    f4.j[1] = { (const float4*)Wk, (uint2*)(whi+OKk), (uint2*)(wlo+OKk), nDD4 };
    f4.j[2] = { (const float4*)Wv, (uint2*)(whi+OV),  (uint2*)(wlo+OV),  nDD4 };
    f4.j[3] = { (const float4*)Wo, (uint2*)(whi+OO),  (uint2*)(wlo+OO),  nDD4 };
    f2bf_multi4<<<dim3(nDD4/256, 4), 256>>>(f4);
    F2Params2 f2 = {};
    f2.j[0] = { (const float4*)W1, (uint2*)(whi+O1),  (uint2*)(wlo+O1),  nDF4 };
    f2.j[1] = { (const float4*)W2, (uint2*)(whi+O2),  (uint2*)(wlo+O2),  nDF4 };
    f2bf_multi2<<<dim3(nDF4/256, 2), 256>>>(f2);

    const int nAct4 = NTOK * DMODEL / 4;
    const dim3 gQKV(DMODEL / 128, NTOK / 128, 3);   // MT=4
    const dim3 gD2 (DMODEL / 128, NTOK / 64,  1);   // MT=2
    const dim3 gF  (FFD    / 128, NTOK / 128, 1);   // MT=4
    const dim3 gA(SEQ / 64, NH, BATCH);

    f2bf<<<nAct4/256, 256>>>((const float4*)x, (uint2*)ahi, (uint2*)alo, nAct4);

    for (int i = 0; i < NL; i++) {
        const float* cur = (i == 0) ? x : h;
        const size_t wdd = (size_t)i * DMODEL * DMODEL;
        const size_t wdf = (size_t)i * DMODEL * FFD;

        GemmParams pq = {};
        pq.job[0] = { whi+OQ+wdd,  wlo+OQ+wdd,  bq + i*DMODEL, 0, qhi, qlo, 0.125f, 0 };
        pq.job[1] = { whi+OKk+wdd, wlo+OKk+wdd, bk + i*DMODEL, 0, khi, klo, 1.f,    0 };
        pq.job[2] = { whi+OV+wdd,  wlo+OV+wdd,  bv + i*DMODEL, 0, vhi, vlo, 1.f,    0 };
        hmma_gemm<4><<<gQKV, 128, GEMM_SMEM4>>>(ahi, alo, pq, NTOK, DMODEL, DMODEL);

        attn_hmma<<<gA, 128, ATT_SMEM>>>(qhi, qlo, khi, klo, vhi, vlo, amask, chi, clo);

        GemmParams po = {};
        po.job[0] = { whi+OO+wdd, wlo+OO+wdd, bo + i*DMODEL, tmp, 0, 0, 1.f, 0 };
        hmma_gemm<2><<<gD2, 128, GEMM_SMEM2>>>(chi, clo, po, NTOK, DMODEL, DMODEL);

        add_ln_kernel<<<NTOK, 192>>>(tmp, cur, ln1g + i*DMODEL, ln1b + i*DMODEL,
                                     h2, ahi, alo);

        GemmParams p1 = {};
        p1.job[0] = { whi+O1+wdf, wlo+O1+wdf, b1 + i*FFD, 0, fhi, flo, 1.f, 1 };
        hmma_gemm<4><<<gF, 128, GEMM_SMEM4>>>(ahi, alo, p1, NTOK, FFD, DMODEL);

        GemmParams p2 = {};
        p2.job[0] = { whi+O2+wdf, wlo+O2+wdf, b2 + i*DMODEL, tmp, 0, 0, 1.f, 0 };
        hmma_gemm<2><<<gD2, 128, GEMM_SMEM2>>>(fhi, flo, p2, NTOK, DMODEL, FFD);

        float* dst = (i == NL - 1) ? out : h;
        add_ln_kernel<<<NTOK, 192>>>(tmp, h2, ln2g + i*DMODEL, ln2b + i*DMODEL,
                                     dst, (i < NL-1) ? ahi : 0, (i < NL-1) ? alo : 0);
    }
}

// round 15
// speedup vs baseline: 1.0151x; 1.0151x over previous
#include <cuda_runtime.h>
#include <cuda_bf16.h>
#include <math.h>
#include <stdint.h>

#define DMODEL 768
#define FFD    3072
#define NL     6
#define NH     12
#define DH     64
#define SEQ    512
#define BATCH  8
#define NTOK   (BATCH*SEQ)   // 4096

#define SZ_DD  (NL*DMODEL*DMODEL)
#define SZ_DF  (NL*DMODEL*FFD)
#define OQ 0
#define OKk (SZ_DD)
#define OV  (2*SZ_DD)
#define OO  (3*SZ_DD)
#define O1  (4*SZ_DD)
#define O2  (4*SZ_DD + SZ_DF)
#define WTOT (4*SZ_DD + 2*SZ_DF)

// ---------------- scratch (static device globals; no runtime allocation) ----
__device__ float g_h  [NTOK*DMODEL];
__device__ float g_h2 [NTOK*DMODEL];
__device__ float g_tmp[NTOK*DMODEL];
__device__ __nv_bfloat16 g_whi[WTOT];
__device__ __nv_bfloat16 g_wlo[WTOT];
__device__ __nv_bfloat16 g_ahi[NTOK*DMODEL];
__device__ __nv_bfloat16 g_alo[NTOK*DMODEL];
__device__ __nv_bfloat16 g_qhi[NTOK*DMODEL];
__device__ __nv_bfloat16 g_qlo[NTOK*DMODEL];
__device__ __nv_bfloat16 g_khi[NTOK*DMODEL];
__device__ __nv_bfloat16 g_klo[NTOK*DMODEL];
__device__ __nv_bfloat16 g_vhi[NTOK*DMODEL];
__device__ __nv_bfloat16 g_vlo[NTOK*DMODEL];
__device__ __nv_bfloat16 g_chi[NTOK*DMODEL];
__device__ __nv_bfloat16 g_clo[NTOK*DMODEL];
__device__ __nv_bfloat16 g_fhi[NTOK*FFD];
__device__ __nv_bfloat16 g_flo[NTOK*FFD];

// ================= helpers ==================================================
__device__ __forceinline__ uint32_t smem_u32(const void* p) {
    uint32_t a;
    asm("{ .reg .u64 t; cvta.to.shared.u64 t, %1; cvt.u32.u64 %0, t; }"
        : "=r"(a) : "l"(p));
    return a;
}
__device__ __forceinline__ uint32_t packbf(float x, float y) {
    __nv_bfloat162 t = __floats2bfloat162_rn(x, y);
    return *(uint32_t*)&t;
}
__device__ __forceinline__ void cpa16(uint32_t dst, const void* src) {
    asm volatile("cp.async.cg.shared.global [%0], [%1], 16;"
                 :: "r"(dst), "l"(src) : "memory");
}
__device__ __forceinline__ void ldsm4(uint32_t* r, uint32_t addr) {
    asm volatile("ldmatrix.sync.aligned.m8n8.x4.shared.b16 {%0,%1,%2,%3}, [%4];"
                 : "=r"(r[0]), "=r"(r[1]), "=r"(r[2]), "=r"(r[3]) : "r"(addr));
}
__device__ __forceinline__ void ldsm4t(uint32_t* r, uint32_t addr) {
    asm volatile("ldmatrix.sync.aligned.m8n8.x4.trans.shared.b16 {%0,%1,%2,%3}, [%4];"
                 : "=r"(r[0]), "=r"(r[1]), "=r"(r[2]), "=r"(r[3]) : "r"(addr));
}
__device__ __forceinline__ void mma16816(float* d, const uint32_t* a,
                                         uint32_t b0, uint32_t b1) {
    asm volatile(
        "mma.sync.aligned.m16n8k16.row.col.f32.bf16.bf16.f32 "
        "{%0,%1,%2,%3}, {%4,%5,%6,%7}, {%8,%9}, {%0,%1,%2,%3};"
        : "+f"(d[0]), "+f"(d[1]), "+f"(d[2]), "+f"(d[3])
        : "r"(a[0]), "r"(a[1]), "r"(a[2]), "r"(a[3]), "r"(b0), "r"(b1));
}

// ================= fp32 -> bf16 hi/lo split conversion ======================
__global__ __launch_bounds__(256)
void f2bf(const float4* __restrict__ in, uint2* __restrict__ hi,
          uint2* __restrict__ lo, int n4)
{
    int i = blockIdx.x * 256 + threadIdx.x;
    if (i >= n4) return;
    float4 f = in[i];
    float hx = __bfloat162float(__float2bfloat16_rn(f.x));
    float hy = __bfloat162float(__float2bfloat16_rn(f.y));
    float hz = __bfloat162float(__float2bfloat16_rn(f.z));
    float hw = __bfloat162float(__float2bfloat16_rn(f.w));
    uint2 H = { packbf(hx, hy), packbf(hz, hw) };
    uint2 Lo = { packbf(f.x - hx, f.y - hy), packbf(f.z - hz, f.w - hw) };
    hi[i] = H;
    lo[i] = Lo;
}

// ================= split-bf16 HMMA GEMM (templated M-tile) ==================
struct GemmJob {
    const __nv_bfloat16 *Bh, *Bl;
    const float* bias;
    float* C;
    __nv_bfloat16 *Chi, *Clo;
    float scale;
    int act;
};
struct GemmParams { GemmJob job[3]; };

template <int MT>
__global__ __launch_bounds__(128, (MT == 2) ? 3 : 2)
void hmma_gemm(const __nv_bfloat16* __restrict__ Ahi,
               const __nv_bfloat16* __restrict__ Alo,
               GemmParams P, int M, int N, int K)
{
    constexpr int ASEC = MT * 2560;
    constexpr int BOFF = 2 * ASEC;
    constexpr int STG  = 2 * ASEC + 16384;
    constexpr int CTAM = MT * 32;

    extern __shared__ char dsm[];
    const GemmJob& J = P.job[blockIdx.z];
    const __nv_bfloat16* __restrict__ Bhi = J.Bh;
    const __nv_bfloat16* __restrict__ Blo = J.Bl;

    const uint32_t sb = smem_u32(dsm);
    const int tid = threadIdx.x;
    const int wid = tid >> 5, L = tid & 31;
    const int wm = wid & 1, wn = wid >> 1;
    const int row0 = blockIdx.y * CTAM, col0 = blockIdx.x * 128;

    float acc[MT][8][4];
    #pragma unroll
    for (int i = 0; i < MT; i++)
        #pragma unroll
        for (int j = 0; j < 8; j++)
            #pragma unroll
            for (int t = 0; t < 4; t++) acc[i][j][t] = 0.f;

    const int aR = tid >> 2, aU = tid & 3;
    const int bR = tid >> 4, bU = tid & 15;
    const uint32_t aDst = (uint32_t)(aR * 80 + aU * 16);
    const uint32_t bDst = (uint32_t)(bR * 256 + ((bU ^ (bR & 7)) << 4));

    const __nv_bfloat16* aHb = Ahi + (size_t)(row0 + aR) * K + aU * 8;
    const __nv_bfloat16* aLb = Alo + (size_t)(row0 + aR) * K + aU * 8;
    const __nv_bfloat16* bHb = Bhi + (size_t)bR * N + col0 + bU * 8;
    const __nv_bfloat16* bLb = Blo + (size_t)bR * N + col0 + bU * 8;

    const int KB = K >> 5;

    #define ISSUE(kb) do {                                                    \
        const uint32_t stg_ = sb + (uint32_t)((kb) & 1) * STG;                \
        const int k0_ = (kb) * 32;                                            \
        _Pragma("unroll")                                                     \
        for (int p = 0; p < MT; p++) {                                        \
            cpa16(stg_ + aDst + p * 2560,        aHb + k0_ + (size_t)(p*32) * K); \
            cpa16(stg_ + ASEC + aDst + p * 2560, aLb + k0_ + (size_t)(p*32) * K); \
        }                                                                     \
        _Pragma("unroll")                                                     \
        for (int p = 0; p < 4; p++) {                                         \
            cpa16(stg_ + BOFF + bDst + p * 2048,        bHb + (size_t)(k0_ + p*8) * N); \
            cpa16(stg_ + BOFF + 8192 + bDst + p * 2048, bLb + (size_t)(k0_ + p*8) * N); \
        }                                                                     \
        asm volatile("cp.async.commit_group;" ::: "memory");                  \
    } while (0)

    ISSUE(0);

    const uint32_t aLane = (uint32_t)((wm * (MT*16) + (L & 15)) * 80 + ((L >> 4) << 4));
    const uint32_t bRow  = (uint32_t)(L & 15);
    const uint32_t bSwzX = (uint32_t)(L & 7);
    const uint32_t bUL   = (uint32_t)(wn * 8 + (L >> 4));

    for (int kb = 0; kb < KB; kb++) {
        const uint32_t stg = sb + (uint32_t)(kb & 1) * STG;
        asm volatile("cp.async.wait_group 0;" ::: "memory");
        __syncthreads();
        if (kb + 1 < KB) ISSUE(kb + 1);

        #pragma unroll
        for (int ks = 0; ks < 2; ks++) {
            uint32_t ah[MT][4], al[MT][4];
            #pragma unroll
            for (int mt = 0; mt < MT; mt++) {
                uint32_t off = aLane + (uint32_t)(mt * 16 * 80 + ks * 32);
                ldsm4(ah[mt], stg + off);
                ldsm4(al[mt], stg + ASEC + off);
            }
            #pragma unroll
            for (int nj = 0; nj < 8; nj += 2) {
                uint32_t bh[4], bl[4];
                uint32_t off = (uint32_t)(ks * 16 + bRow) * 256
                             + (((bUL + nj) ^ bSwzX) << 4);
                ldsm4t(bh, stg + BOFF + off);
                ldsm4t(bl, stg + BOFF + 8192 + off);
                #pragma unroll
                for (int mt = 0; mt < MT; mt++) {
                    mma16816(acc[mt][nj],   ah[mt], bh[0], bh[1]);
                    mma16816(acc[mt][nj+1], ah[mt], bh[2], bh[3]);
                    mma16816(acc[mt][nj],   ah[mt], bl[0], bl[1]);
                    mma16816(acc[mt][nj+1], ah[mt], bl[2], bl[3]);
                    mma16816(acc[mt][nj],   al[mt], bh[0], bh[1]);
                    mma16816(acc[mt][nj+1], al[mt], bh[2], bh[3]);
                }
            }
        }
        __syncthreads();
    }
    #undef ISSUE

    // ---- single-pass epilogue: all warps write, 1 sync, 1 store pass -------
    const float* bias = J.bias;
    float* C = J.C;
    __nv_bfloat16 *Chi = J.Chi, *Clo = J.Clo;
    const float scale = J.scale;
    const int act = J.act;

    float* sOut = (float*)dsm;               // CTAM x 132 fp32
    const int gid = L >> 2, tig = L & 3;
    #pragma unroll
    for (int mt = 0; mt < MT; mt++) {
        #pragma unroll
        for (int nt = 0; nt < 8; nt++) {
            const int srow = wm * (MT*16) + mt * 16 + gid;
            const int scol = wn * 64 + nt * 8 + tig * 2;
            const int gc   = col0 + scol;
            float b0v = bias[gc], b1v = bias[gc + 1];
            float v0 = (acc[mt][nt][0] + b0v) * scale;
            float v1 = (acc[mt][nt][1] + b1v) * scale;
            float v2 = (acc[mt][nt][2] + b0v) * scale;
            float v3 = (acc[mt][nt][3] + b1v) * scale;
            if (act) {
                v0 = 0.5f*v0*(1.f+erff(v0*0.70710678118654752f));
                v1 = 0.5f*v1*(1.f+erff(v1*0.70710678118654752f));
                v2 = 0.5f*v2*(1.f+erff(v2*0.70710678118654752f));
                v3 = 0.5f*v3*(1.f+erff(v3*0.70710678118654752f));
            }
            sOut[srow * 132 + scol]       = v0;
            sOut[srow * 132 + scol + 1]   = v1;
            sOut[(srow+8) * 132 + scol]   = v2;
            sOut[(srow+8) * 132 + scol+1] = v3;
        }
    }
    __syncthreads();
    #pragma unroll
    for (int i = 0; i < MT*8; i++) {
        const int f   = tid + i * 128;
        const int row = f >> 5;
        const int c4  = (f & 31) * 4;
        float4 v = *(const float4*)(sOut + row * 132 + c4);
        const size_t gidx = (size_t)(row0 + row) * N + col0 + c4;
        if (C) *(float4*)(C + gidx) = v;
        if (Chi) {
            float hx = __bfloat162float(__float2bfloat16_rn(v.x));
            float hy = __bfloat162float(__float2bfloat16_rn(v.y));
            float hz = __bfloat162float(__float2bfloat16_rn(v.z));
            float hw = __bfloat162float(__float2bfloat16_rn(v.w));
            uint2 H = { packbf(hx, hy), packbf(hz, hw) };
            uint2 Lo = { packbf(v.x - hx, v.y - hy), packbf(v.z - hz, v.w - hw) };
            *(uint2*)(Chi + gidx) = H;
            *(uint2*)(Clo + gidx) = Lo;
        }
    }
}

#define GEMM_SMEM4 (2*(4*2560*2 + 16384))   // 73728  (sOut 128x132 = 67584 fits)
#define GEMM_SMEM2 (2*(2*2560*2 + 16384))   // 53248  (sOut 64x132 = 33792 fits)

// ================= HMMA flash attention (R8/R10 version) ====================
#define ATT_SMEM (49152 + 256)

__global__ __launch_bounds__(128, 3)
void attn_hmma(const __nv_bfloat16* __restrict__ Qh, const __nv_bfloat16* __restrict__ Ql,
               const __nv_bfloat16* __restrict__ Kh, const __nv_bfloat16* __restrict__ Kl,
               const __nv_bfloat16* __restrict__ Vh, const __nv_bfloat16* __restrict__ Vl,
               const int* __restrict__ mask,
               __nv_bfloat16* __restrict__ Ohi, __nv_bfloat16* __restrict__ Olo)
{
    extern __shared__ char sm[];
    const uint32_t sb = smem_u32(sm);
    float* msk_s = (float*)(sm + 49152);
    const int tid = threadIdx.x, w = tid >> 5, L = tid & 31;
    const int qt = blockIdx.x, hh = blockIdx.y, b = blockIdx.z;
    const size_t base = (size_t)b * SEQ * DMODEL + (size_t)hh * DH;

    {
        const __nv_bfloat16* qh = Qh + base + (size_t)(qt * 64) * DMODEL;
        const __nv_bfloat16* ql = Ql + base + (size_t)(qt * 64) * DMODEL;
        #pragma unroll
        for (int it = 0; it < 4; it++) {
            int u = tid + it * 128;
            int r = u >> 3, c = u & 7;
            uint32_t off = (uint32_t)(r * 128 + ((c ^ (r & 7)) << 4));
            *(uint4*)(sm + off)        = *(const uint4*)(qh + (size_t)r * DMODEL + c * 8);
            *(uint4*)(sm + 8192 + off) = *(const uint4*)(ql + (size_t)r * DMODEL + c * 8);
        }
    }

    float m0 = -1e30f, m1 = -1e30f, l0 = 0.f, l1 = 0.f;
    float o[8][4];
    #pragma unroll
    for (int f = 0; f < 8; f++)
        #pragma unroll
        for (int t = 0; t < 4; t++) o[f][t] = 0.f;

    for (int kt = 0; kt < SEQ / 64; kt++) {
        __syncthreads();
        {
            const size_t kb = base + (size_t)(kt * 64) * DMODEL;
            #pragma unroll
            for (int it = 0; it < 4; it++) {
                int u = tid + it * 128;
                int r = u >> 3, c = u & 7;
                uint32_t off = (uint32_t)(r * 128 + ((c ^ (r & 7)) << 4));
                size_t g = kb + (size_t)r * DMODEL + c * 8;
                *(uint4*)(sm + 16384 + off) = *(const uint4*)(Kh + g);
                *(uint4*)(sm + 24576 + off) = *(const uint4*)(Kl + g);
                *(uint4*)(sm + 32768 + off) = *(const uint4*)(Vh + g);
                *(uint4*)(sm + 40960 + off) = *(const uint4*)(Vl + g);
            }
            if (tid < 64) msk_s[tid] = (float)mask[b * SEQ + kt * 64 + tid];
        }
        __syncthreads();

        float s[8][4];
        #pragma unroll
        for (int f = 0; f < 8; f++)
            #pragma unroll
            for (int t = 0; t < 4; t++) s[f][t] = 0.f;

        #pragma unroll
        for (int ks = 0; ks < 4; ks++) {
            const int qrow = w * 16 + (L & 15);
            const uint32_t qoff = (uint32_t)(qrow * 128
                                  + (((ks * 2 + (L >> 4)) ^ (qrow & 7)) << 4));
            uint32_t qhf[4], qlf[4];
            ldsm4(qhf, sb + qoff);
            ldsm4(qlf, sb + 8192 + qoff);
            #pragma unroll
            for (int nj = 0; nj < 4; nj++) {
                const int krow = nj * 16 + (L & 7) + ((L >> 4) << 3);
                const uint32_t koff = (uint32_t)(krow * 128
                                      + (((ks * 2 + ((L >> 3) & 1)) ^ (krow & 7)) << 4));
                uint32_t khf[4], klf[4];
                ldsm4(khf, sb + 16384 + koff);
                ldsm4(klf, sb + 24576 + koff);
                mma16816(s[2*nj],   qhf, khf[0], khf[1]);
                mma16816(s[2*nj+1], qhf, khf[2], khf[3]);
                mma16816(s[2*nj],   qhf, klf[0], klf[1]);
                mma16816(s[2*nj+1], qhf, klf[2], klf[3]);
                mma16816(s[2*nj],   qlf, khf[0], khf[1]);
                mma16816(s[2*nj+1], qlf, khf[2], khf[3]);
            }
        }

        #pragma unroll
        for (int f = 0; f < 8; f++) {
            float mk0 = msk_s[f * 8 + 2 * (L & 3)];
            float mk1 = msk_s[f * 8 + 2 * (L & 3) + 1];
            if (mk0 == 0.f) { s[f][0] = -1e9f; s[f][2] = -1e9f; }
            if (mk1 == 0.f) { s[f][1] = -1e9f; s[f][3] = -1e9f; }
        }

        float mx0 = -1e30f, mx1 = -1e30f;
        #pragma unroll
        for (int f = 0; f < 8; f++) {
            mx0 = fmaxf(mx0, fmaxf(s[f][0], s[f][1]));
            mx1 = fmaxf(mx1, fmaxf(s[f][2], s[f][3]));
        }
        #pragma unroll
        for (int ofs = 1; ofs <= 2; ofs <<= 1) {
            mx0 = fmaxf(mx0, __shfl_xor_sync(0xffffffffu, mx0, ofs, 4));
            mx1 = fmaxf(mx1, __shfl_xor_sync(0xffffffffu, mx1, ofs, 4));
        }
        float mn0 = fmaxf(m0, mx0), mn1 = fmaxf(m1, mx1);
        float al0 = __expf(m0 - mn0), al1 = __expf(m1 - mn1);
        m0 = mn0; m1 = mn1;
        float sum0 = 0.f, sum1 = 0.f;
        #pragma unroll
        for (int f = 0; f < 8; f++) {
            s[f][0] = __expf(s[f][0] - mn0); sum0 += s[f][0];
            s[f][1] = __expf(s[f][1] - mn0); sum0 += s[f][1];
            s[f][2] = __expf(s[f][2] - mn1); sum1 += s[f][2];
            s[f][3] = __expf(s[f][3] - mn1); sum1 += s[f][3];
        }
        #pragma unroll
        for (int ofs = 1; ofs <= 2; ofs <<= 1) {
            sum0 += __shfl_xor_sync(0xffffffffu, sum0, ofs, 4);
            sum1 += __shfl_xor_sync(0xffffffffu, sum1, ofs, 4);
        }
        l0 = l0 * al0 + sum0;
        l1 = l1 * al1 + sum1;
        #pragma unroll
        for (int f = 0; f < 8; f++) {
            o[f][0] *= al0; o[f][1] *= al0; o[f][2] *= al1; o[f][3] *= al1;
        }

        #pragma unroll
        for (int s4 = 0; s4 < 4; s4++) {
            uint32_t ph[4], pl[4];
            {
                float p00 = s[2*s4][0],   p01 = s[2*s4][1];
                float p02 = s[2*s4][2],   p03 = s[2*s4][3];
                float p10 = s[2*s4+1][0], p11 = s[2*s4+1][1];
                float p12 = s[2*s4+1][2], p13 = s[2*s4+1][3];
                ph[0] = packbf(p00, p01); ph[1] = packbf(p02, p03);
                ph[2] = packbf(p10, p11); ph[3] = packbf(p12, p13);
                pl[0] = packbf(p00 - __bfloat162float(__float2bfloat16_rn(p00)),
                               p01 - __bfloat162float(__float2bfloat16_rn(p01)));
                pl[1] = packbf(p02 - __bfloat162float(__float2bfloat16_rn(p02)),
                               p03 - __bfloat162float(__float2bfloat16_rn(p03)));
                pl[2] = packbf(p10 - __bfloat162float(__float2bfloat16_rn(p10)),
                               p11 - __bfloat162float(__float2bfloat16_rn(p11)));
                pl[3] = packbf(p12 - __bfloat162float(__float2bfloat16_rn(p12)),
                               p13 - __bfloat162float(__float2bfloat16_rn(p13)));
            }
            #pragma unroll
            for (int dj = 0; dj < 4; dj++) {
                const int vrow = s4 * 16 + (L & 15);
                const uint32_t voff = (uint32_t)(vrow * 128
                                      + (((dj * 2 + (L >> 4)) ^ (vrow & 7)) << 4));
                uint32_t vhf[4], vlf[4];
                ldsm4t(vhf, sb + 32768 + voff);
                ldsm4t(vlf, sb + 40960 + voff);
                mma16816(o[2*dj],   ph, vhf[0], vhf[1]);
                mma16816(o[2*dj+1], ph, vhf[2], vhf[3]);
                mma16816(o[2*dj],   ph, vlf[0], vlf[1]);
                mma16816(o[2*dj+1], ph, vlf[2], vlf[3]);
                mma16816(o[2*dj],   pl, vhf[0], vhf[1]);
                mma16816(o[2*dj+1], pl, vhf[2], vhf[3]);
            }
        }
    }

    const float inv0 = 1.f / l0, inv1 = 1.f / l1;
    const int r0 = qt * 64 + w * 16 + (L >> 2);
    #pragma unroll
    for (int f = 0; f < 8; f++) {
        const int c = f * 8 + 2 * (L & 3);
        const size_t i0 = base + (size_t)r0 * DMODEL + c;
        const size_t i1 = base + (size_t)(r0 + 8) * DMODEL + c;
        float v0 = o[f][0] * inv0, v1 = o[f][1] * inv0;
        float v2 = o[f][2] * inv1, v3 = o[f][3] * inv1;
        float h0 = __bfloat162float(__float2bfloat16_rn(v0));
        float h1 = __bfloat162float(__float2bfloat16_rn(v1));
        float h2v = __bfloat162float(__float2bfloat16_rn(v2));
        float h3 = __bfloat162float(__float2bfloat16_rn(v3));
        *(uint32_t*)(Ohi + i0) = packbf(v0, v1);
        *(uint32_t*)(Olo + i0) = packbf(v0 - h0, v1 - h1);
        *(uint32_t*)(Ohi + i1) = packbf(v2, v3);
        *(uint32_t*)(Olo + i1) = packbf(v2 - h2v, v3 - h3);
    }
}

// ---------------- residual add + LayerNorm (float4, 192 threads/row) --------
__device__ __forceinline__ float blockReduceSum6(float val)
{
    __shared__ float red[6];
    __syncthreads();
    int lane = threadIdx.x & 31, wid = threadIdx.x >> 5;
    #pragma unroll
    for (int o = 16; o > 0; o >>= 1) val += __shfl_down_sync(0xffffffffu, val, o);
    if (lane == 0) red[wid] = val;
    __syncthreads();
    if (wid == 0) {
        val = (lane < 6) ? red[lane] : 0.f;
        #pragma unroll
        for (int o = 4; o > 0; o >>= 1) val += __shfl_down_sync(0xffffffffu, val, o);
        if (lane == 0) red[0] = val;
    }
    __syncthreads();
    return red[0];
}

__global__ __launch_bounds__(192)
void add_ln_kernel(const float* __restrict__ a, const float* __restrict__ res,
                   const float* __restrict__ g, const float* __restrict__ bt,
                   float* __restrict__ out,
                   __nv_bfloat16* __restrict__ ohi, __nv_bfloat16* __restrict__ olo)
{
    const int row = blockIdx.x;
    const int c4 = threadIdx.x * 4;
    const size_t rb = (size_t)row * DMODEL + c4;

    float4 av = *(const float4*)(a + rb);
    float4 rv = *(const float4*)(res + rb);
    float v0 = av.x + rv.x, v1 = av.y + rv.y, v2 = av.z + rv.z, v3 = av.w + rv.w;

    float sum = blockReduceSum6(v0 + v1 + v2 + v3);
    const float mu = sum * (1.f / DMODEL);
    float d0 = v0 - mu, d1 = v1 - mu, d2 = v2 - mu, d3 = v3 - mu;
    float s2 = blockReduceSum6(d0*d0 + d1*d1 + d2*d2 + d3*d3);
    const float rs = rsqrtf(s2 * (1.f / DMODEL) + 1e-12f);

    float4 gv = *(const float4*)(g + c4);
    float4 bv = *(const float4*)(bt + c4);
    float o0 = d0 * rs * gv.x + bv.x;
    float o1 = d1 * rs * gv.y + bv.y;
    float o2 = d2 * rs * gv.z + bv.z;
    float o3 = d3 * rs * gv.w + bv.w;
    float4 ov = { o0, o1, o2, o3 };
    *(float4*)(out + rb) = ov;
    if (ohi) {
        float h0 = __bfloat162float(__float2bfloat16_rn(o0));
        float h1 = __bfloat162float(__float2bfloat16_rn(o1));
        float h2 = __bfloat162float(__float2bfloat16_rn(o2));
        float h3 = __bfloat162float(__float2bfloat16_rn(o3));
        uint2 H  = { packbf(o0, o1), packbf(o2, o3) };
        uint2 Lo = { packbf(o0 - h0, o1 - h1), packbf(o2 - h2, o3 - h3) };
        *(uint2*)(ohi + rb) = H;
        *(uint2*)(olo + rb) = Lo;
    }
}

// ---------------- driver -----------------------------------------------------
extern "C" void kernel_launch(void* const* d_in, const int* in_sizes, int n_in,
                              void* d_out, int out_size)
{
    const float* x     = (const float*)d_in[0];
    const int*   amask = (const int*)  d_in[1];
    const float* Wq    = (const float*)d_in[2];
    const float* bq    = (const float*)d_in[3];
    const float* Wk    = (const float*)d_in[4];
    const float* bk    = (const float*)d_in[5];
    const float* Wv    = (const float*)d_in[6];
    const float* bv    = (const float*)d_in[7];
    const float* Wo    = (const float*)d_in[8];
    const float* bo    = (const float*)d_in[9];
    const float* ln1g  = (const float*)d_in[10];
    const float* ln1b  = (const float*)d_in[11];
    const float* W1    = (const float*)d_in[12];
    const float* b1    = (const float*)d_in[13];
    const float* W2    = (const float*)d_in[14];
    const float* b2    = (const float*)d_in[15];
    const float* ln2g  = (const float*)d_in[16];
    const float* ln2b  = (const float*)d_in[17];
    float* out = (float*)d_out;

    float *h, *h2, *tmp;
    __nv_bfloat16 *whi, *wlo, *ahi, *alo, *chi, *clo, *fhi, *flo;
    __nv_bfloat16 *qhi, *qlo, *khi, *klo, *vhi, *vlo;
    cudaGetSymbolAddress((void**)&h,   g_h);
    cudaGetSymbolAddress((void**)&h2,  g_h2);
    cudaGetSymbolAddress((void**)&tmp, g_tmp);
    cudaGetSymbolAddress((void**)&whi, g_whi);
    cudaGetSymbolAddress((void**)&wlo, g_wlo);
    cudaGetSymbolAddress((void**)&ahi, g_ahi);
    cudaGetSymbolAddress((void**)&alo, g_alo);
    cudaGetSymbolAddress((void**)&qhi, g_qhi);
    cudaGetSymbolAddress((void**)&qlo, g_qlo);
    cudaGetSymbolAddress((void**)&khi, g_khi);
    cudaGetSymbolAddress((void**)&klo, g_klo);
    cudaGetSymbolAddress((void**)&vhi, g_vhi);
    cudaGetSymbolAddress((void**)&vlo, g_vlo);
    cudaGetSymbolAddress((void**)&chi, g_chi);
    cudaGetSymbolAddress((void**)&clo, g_clo);
    cudaGetSymbolAddress((void**)&fhi, g_fhi);
    cudaGetSymbolAddress((void**)&flo, g_flo);

    cudaFuncSetAttribute(hmma_gemm<4>, cudaFuncAttributeMaxDynamicSharedMemorySize, GEMM_SMEM4);
    cudaFuncSetAttribute(hmma_gemm<2>, cudaFuncAttributeMaxDynamicSharedMemorySize, GEMM_SMEM2);
    cudaFuncSetAttribute(attn_hmma, cudaFuncAttributeMaxDynamicSharedMemorySize, ATT_SMEM);

    const int nDD4 = SZ_DD / 4;
    const int nDF4 = SZ_DF / 4;
    f2bf<<<nDD4/256, 256>>>((const float4*)Wq, (uint2*)(whi+OQ),  (uint2*)(wlo+OQ),  nDD4);
    f2bf<<<nDD4/256, 256>>>((const float4*)Wk, (uint2*)(whi+OKk), (uint2*)(wlo+OKk), nDD4);
    f2bf<<<nDD4/256, 256>>>((const float4*)Wv, (uint2*)(whi+OV),  (uint2*)(wlo+OV),  nDD4);
    f2bf<<<nDD4/256, 256>>>((const float4*)Wo, (uint2*)(whi+OO),  (uint2*)(wlo+OO),  nDD4);
    f2bf<<<nDF4/256, 256>>>((const float4*)W1, (uint2*)(whi+O1),  (uint2*)(wlo+O1),  nDF4);
    f2bf<<<nDF4/256, 256>>>((const float4*)W2, (uint2*)(whi+O2),  (uint2*)(wlo+O2),  nDF4);

    const int nAct4 = NTOK * DMODEL / 4;
    const dim3 gQKV(DMODEL / 128, NTOK / 128, 3);   // MT=4
    const dim3 gD2 (DMODEL / 128, NTOK / 64,  1);   // MT=2
    const dim3 gF  (FFD    / 128, NTOK / 128, 1);   // MT=4
    const dim3 gA(SEQ / 64, NH, BATCH);

    f2bf<<<nAct4/256, 256>>>((const float4*)x, (uint2*)ahi, (uint2*)alo, nAct4);

    for (int i = 0; i < NL; i++) {
        const float* cur = (i == 0) ? x : h;
        const size_t wdd = (size_t)i * DMODEL * DMODEL;
        const size_t wdf = (size_t)i * DMODEL * FFD;

        GemmParams pq = {};
        pq.job[0] = { whi+OQ+wdd,  wlo+OQ+wdd,  bq + i*DMODEL, 0, qhi, qlo, 0.125f, 0 };
        pq.job[1] = { whi+OKk+wdd, wlo+OKk+wdd, bk + i*DMODEL, 0, khi, klo, 1.f,    0 };
        pq.job[2] = { whi+OV+wdd,  wlo+OV+wdd,  bv + i*DMODEL, 0, vhi, vlo, 1.f,    0 };
        hmma_gemm<4><<<gQKV, 128, GEMM_SMEM4>>>(ahi, alo, pq, NTOK, DMODEL, DMODEL);

        attn_hmma<<<gA, 128, ATT_SMEM>>>(qhi, qlo, khi, klo, vhi, vlo, amask, chi, clo);

        GemmParams po = {};
        po.job[0] = { whi+OO+wdd, wlo+OO+wdd, bo + i*DMODEL, tmp, 0, 0, 1.f, 0 };
        hmma_gemm<2><<<gD2, 128, GEMM_SMEM2>>>(chi, clo, po, NTOK, DMODEL, DMODEL);

        add_ln_kernel<<<NTOK, 192>>>(tmp, cur, ln1g + i*DMODEL, ln1b + i*DMODEL,
                                     h2, ahi, alo);

        GemmParams p1 = {};
        p1.job[0] = { whi+O1+wdf, wlo+O1+wdf, b1 + i*FFD, 0, fhi, flo, 1.f, 1 };
        hmma_gemm<4><<<gF, 128, GEMM_SMEM4>>>(ahi, alo, p1, NTOK, FFD, DMODEL);

        GemmParams p2 = {};
        p2.job[0] = { whi+O2+wdf, wlo+O2+wdf, b2 + i*DMODEL, tmp, 0, 0, 1.f, 0 };
        hmma_gemm<2><<<gD2, 128, GEMM_SMEM2>>>(fhi, flo, p2, NTOK, DMODEL, FFD);

        float* dst = (i == NL - 1) ? out : h;
        add_ln_kernel<<<NTOK, 192>>>(tmp, h2, ln2g + i*DMODEL, ln2b + i*DMODEL,
                                     dst, (i < NL-1) ? ahi : 0, (i < NL-1) ? alo : 0);
    }
}

// round 16
// speedup vs baseline: 1.0164x; 1.0012x over previous
#include <cuda_runtime.h>
#include <cuda_bf16.h>
#include <math.h>
#include <stdint.h>

#define DMODEL 768
#define FFD    3072
#define NL     6
#define NH     12
#define DH     64
#define SEQ    512
#define BATCH  8
#define NTOK   (BATCH*SEQ)   // 4096

#define SZ_DD  (NL*DMODEL*DMODEL)
#define SZ_DF  (NL*DMODEL*FFD)
#define OQ 0
#define OKk (SZ_DD)
#define OV  (2*SZ_DD)
#define OO  (3*SZ_DD)
#define O1  (4*SZ_DD)
#define O2  (4*SZ_DD + SZ_DF)
#define WTOT (4*SZ_DD + 2*SZ_DF)

// ---------------- scratch (static device globals; no runtime allocation) ----
__device__ float g_h  [NTOK*DMODEL];
__device__ float g_h2 [NTOK*DMODEL];
__device__ float g_tmp[NTOK*DMODEL];
__device__ __nv_bfloat16 g_whi[WTOT];
__device__ __nv_bfloat16 g_wlo[WTOT];
__device__ __nv_bfloat16 g_ahi[NTOK*DMODEL];
__device__ __nv_bfloat16 g_alo[NTOK*DMODEL];
__device__ __nv_bfloat16 g_qhi[NTOK*DMODEL];
__device__ __nv_bfloat16 g_qlo[NTOK*DMODEL];
__device__ __nv_bfloat16 g_khi[NTOK*DMODEL];
__device__ __nv_bfloat16 g_klo[NTOK*DMODEL];
__device__ __nv_bfloat16 g_vhi[NTOK*DMODEL];
__device__ __nv_bfloat16 g_vlo[NTOK*DMODEL];
__device__ __nv_bfloat16 g_chi[NTOK*DMODEL];
__device__ __nv_bfloat16 g_clo[NTOK*DMODEL];
__device__ __nv_bfloat16 g_fhi[NTOK*FFD];
__device__ __nv_bfloat16 g_flo[NTOK*FFD];

// ================= helpers ==================================================
__device__ __forceinline__ uint32_t smem_u32(const void* p) {
    uint32_t a;
    asm("{ .reg .u64 t; cvta.to.shared.u64 t, %1; cvt.u32.u64 %0, t; }"
        : "=r"(a) : "l"(p));
    return a;
}
__device__ __forceinline__ uint32_t packbf(float x, float y) {
    __nv_bfloat162 t = __floats2bfloat162_rn(x, y);
    return *(uint32_t*)&t;
}
__device__ __forceinline__ void cpa16(uint32_t dst, const void* src) {
    asm volatile("cp.async.cg.shared.global [%0], [%1], 16;"
                 :: "r"(dst), "l"(src) : "memory");
}
__device__ __forceinline__ void ldsm4(uint32_t* r, uint32_t addr) {
    asm volatile("ldmatrix.sync.aligned.m8n8.x4.shared.b16 {%0,%1,%2,%3}, [%4];"
                 : "=r"(r[0]), "=r"(r[1]), "=r"(r[2]), "=r"(r[3]) : "r"(addr));
}
__device__ __forceinline__ void ldsm4t(uint32_t* r, uint32_t addr) {
    asm volatile("ldmatrix.sync.aligned.m8n8.x4.trans.shared.b16 {%0,%1,%2,%3}, [%4];"
                 : "=r"(r[0]), "=r"(r[1]), "=r"(r[2]), "=r"(r[3]) : "r"(addr));
}
__device__ __forceinline__ void mma16816(float* d, const uint32_t* a,
                                         uint32_t b0, uint32_t b1) {
    asm volatile(
        "mma.sync.aligned.m16n8k16.row.col.f32.bf16.bf16.f32 "
        "{%0,%1,%2,%3}, {%4,%5,%6,%7}, {%8,%9}, {%0,%1,%2,%3};"
        : "+f"(d[0]), "+f"(d[1]), "+f"(d[2]), "+f"(d[3])
        : "r"(a[0]), "r"(a[1]), "r"(a[2]), "r"(a[3]), "r"(b0), "r"(b1));
}

// ================= fp32 -> bf16 hi/lo split conversion ======================
__global__ __launch_bounds__(256)
void f2bf(const float4* __restrict__ in, uint2* __restrict__ hi,
          uint2* __restrict__ lo, int n4)
{
    int i = blockIdx.x * 256 + threadIdx.x;
    if (i >= n4) return;
    float4 f = in[i];
    float hx = __bfloat162float(__float2bfloat16_rn(f.x));
    float hy = __bfloat162float(__float2bfloat16_rn(f.y));
    float hz = __bfloat162float(__float2bfloat16_rn(f.z));
    float hw = __bfloat162float(__float2bfloat16_rn(f.w));
    uint2 H = { packbf(hx, hy), packbf(hz, hw) };
    uint2 Lo = { packbf(f.x - hx, f.y - hy), packbf(f.z - hz, f.w - hw) };
    hi[i] = H;
    lo[i] = Lo;
}

// ================= split-bf16 HMMA GEMM (templated M-tile) ==================
struct GemmJob {
    const __nv_bfloat16 *Bh, *Bl;
    const float* bias;
    float* C;
    __nv_bfloat16 *Chi, *Clo;
    float scale;
    int act;
};
struct GemmParams { GemmJob job[3]; };

template <int MT>
__global__ __launch_bounds__(128, (MT == 2) ? 3 : 2)
void hmma_gemm(const __nv_bfloat16* __restrict__ Ahi,
               const __nv_bfloat16* __restrict__ Alo,
               GemmParams P, int M, int N, int K)
{
    constexpr int ASEC = MT * 2560;
    constexpr int BOFF = 2 * ASEC;
    constexpr int STG  = 2 * ASEC + 16384;
    constexpr int CTAM = MT * 32;

    extern __shared__ char dsm[];
    const GemmJob& J = P.job[blockIdx.z];
    const __nv_bfloat16* __restrict__ Bhi = J.Bh;
    const __nv_bfloat16* __restrict__ Blo = J.Bl;

    const uint32_t sb = smem_u32(dsm);
    const int tid = threadIdx.x;
    const int wid = tid >> 5, L = tid & 31;
    const int wm = wid & 1, wn = wid >> 1;
    const int row0 = blockIdx.y * CTAM, col0 = blockIdx.x * 128;

    float acc[MT][8][4];
    #pragma unroll
    for (int i = 0; i < MT; i++)
        #pragma unroll
        for (int j = 0; j < 8; j++)
            #pragma unroll
            for (int t = 0; t < 4; t++) acc[i][j][t] = 0.f;

    const int aR = tid >> 2, aU = tid & 3;
    const int bR = tid >> 4, bU = tid & 15;
    const uint32_t aDst = (uint32_t)(aR * 80 + aU * 16);
    const uint32_t bDst = (uint32_t)(bR * 256 + ((bU ^ (bR & 7)) << 4));

    const __nv_bfloat16* aHb = Ahi + (size_t)(row0 + aR) * K + aU * 8;
    const __nv_bfloat16* aLb = Alo + (size_t)(row0 + aR) * K + aU * 8;
    const __nv_bfloat16* bHb = Bhi + (size_t)bR * N + col0 + bU * 8;
    const __nv_bfloat16* bLb = Blo + (size_t)bR * N + col0 + bU * 8;

    const int KB = K >> 5;

    #define ISSUE(kb) do {                                                    \
        const uint32_t stg_ = sb + (uint32_t)((kb) & 1) * STG;                \
        const int k0_ = (kb) * 32;                                            \
        _Pragma("unroll")                                                     \
        for (int p = 0; p < MT; p++) {                                        \
            cpa16(stg_ + aDst + p * 2560,        aHb + k0_ + (size_t)(p*32) * K); \
            cpa16(stg_ + ASEC + aDst + p * 2560, aLb + k0_ + (size_t)(p*32) * K); \
        }                                                                     \
        _Pragma("unroll")                                                     \
        for (int p = 0; p < 4; p++) {                                         \
            cpa16(stg_ + BOFF + bDst + p * 2048,        bHb + (size_t)(k0_ + p*8) * N); \
            cpa16(stg_ + BOFF + 8192 + bDst + p * 2048, bLb + (size_t)(k0_ + p*8) * N); \
        }                                                                     \
        asm volatile("cp.async.commit_group;" ::: "memory");                  \
    } while (0)

    ISSUE(0);

    const uint32_t aLane = (uint32_t)((wm * (MT*16) + (L & 15)) * 80 + ((L >> 4) << 4));
    const uint32_t bRow  = (uint32_t)(L & 15);
    const uint32_t bSwzX = (uint32_t)(L & 7);
    const uint32_t bUL   = (uint32_t)(wn * 8 + (L >> 4));

    for (int kb = 0; kb < KB; kb++) {
        const uint32_t stg = sb + (uint32_t)(kb & 1) * STG;
        asm volatile("cp.async.wait_group 0;" ::: "memory");
        __syncthreads();
        if (kb + 1 < KB) ISSUE(kb + 1);

        #pragma unroll
        for (int ks = 0; ks < 2; ks++) {
            uint32_t ah[MT][4], al[MT][4];
            #pragma unroll
            for (int mt = 0; mt < MT; mt++) {
                uint32_t off = aLane + (uint32_t)(mt * 16 * 80 + ks * 32);
                ldsm4(ah[mt], stg + off);
                ldsm4(al[mt], stg + ASEC + off);
            }
            #pragma unroll
            for (int nj = 0; nj < 8; nj += 2) {
                uint32_t bh[4], bl[4];
                uint32_t off = (uint32_t)(ks * 16 + bRow) * 256
                             + (((bUL + nj) ^ bSwzX) << 4);
                ldsm4t(bh, stg + BOFF + off);
                ldsm4t(bl, stg + BOFF + 8192 + off);
                #pragma unroll
                for (int mt = 0; mt < MT; mt++) {
                    mma16816(acc[mt][nj],   ah[mt], bh[0], bh[1]);
                    mma16816(acc[mt][nj+1], ah[mt], bh[2], bh[3]);
                    mma16816(acc[mt][nj],   ah[mt], bl[0], bl[1]);
                    mma16816(acc[mt][nj+1], ah[mt], bl[2], bl[3]);
                    mma16816(acc[mt][nj],   al[mt], bh[0], bh[1]);
                    mma16816(acc[mt][nj+1], al[mt], bh[2], bh[3]);
                }
            }
        }
        __syncthreads();
    }
    #undef ISSUE

    // ---- single-pass epilogue: all warps write, 1 sync, 1 store pass -------
    const float* bias = J.bias;
    float* C = J.C;
    __nv_bfloat16 *Chi = J.Chi, *Clo = J.Clo;
    const float scale = J.scale;
    const int act = J.act;

    float* sOut = (float*)dsm;               // CTAM x 132 fp32
    const int gid = L >> 2, tig = L & 3;
    #pragma unroll
    for (int mt = 0; mt < MT; mt++) {
        #pragma unroll
        for (int nt = 0; nt < 8; nt++) {
            const int srow = wm * (MT*16) + mt * 16 + gid;
            const int scol = wn * 64 + nt * 8 + tig * 2;
            const int gc   = col0 + scol;
            float b0v = bias[gc], b1v = bias[gc + 1];
            float v0 = (acc[mt][nt][0] + b0v) * scale;
            float v1 = (acc[mt][nt][1] + b1v) * scale;
            float v2 = (acc[mt][nt][2] + b0v) * scale;
            float v3 = (acc[mt][nt][3] + b1v) * scale;
            if (act) {
                v0 = 0.5f*v0*(1.f+erff(v0*0.70710678118654752f));
                v1 = 0.5f*v1*(1.f+erff(v1*0.70710678118654752f));
                v2 = 0.5f*v2*(1.f+erff(v2*0.70710678118654752f));
                v3 = 0.5f*v3*(1.f+erff(v3*0.70710678118654752f));
            }
            sOut[srow * 132 + scol]       = v0;
            sOut[srow * 132 + scol + 1]   = v1;
            sOut[(srow+8) * 132 + scol]   = v2;
            sOut[(srow+8) * 132 + scol+1] = v3;
        }
    }
    __syncthreads();
    #pragma unroll
    for (int i = 0; i < MT*8; i++) {
        const int f   = tid + i * 128;
        const int row = f >> 5;
        const int c4  = (f & 31) * 4;
        float4 v = *(const float4*)(sOut + row * 132 + c4);
        const size_t gidx = (size_t)(row0 + row) * N + col0 + c4;
        if (C) *(float4*)(C + gidx) = v;
        if (Chi) {
            float hx = __bfloat162float(__float2bfloat16_rn(v.x));
            float hy = __bfloat162float(__float2bfloat16_rn(v.y));
            float hz = __bfloat162float(__float2bfloat16_rn(v.z));
            float hw = __bfloat162float(__float2bfloat16_rn(v.w));
            uint2 H = { packbf(hx, hy), packbf(hz, hw) };
            uint2 Lo = { packbf(v.x - hx, v.y - hy), packbf(v.z - hz, v.w - hw) };
            *(uint2*)(Chi + gidx) = H;
            *(uint2*)(Clo + gidx) = Lo;
        }
    }
}

#define GEMM_SMEM4 (2*(4*2560*2 + 16384))   // 73728
#define GEMM_SMEM2 (2*(2*2560*2 + 16384))   // 53248

// ================= HMMA flash attention (champion + hoisted mask) ===========
// smem: Qh 0, Ql 8192, Kh 16384, Kl 24576, Vh 32768, Vl 40960, mask @49152
#define ATT_SMEM (49152 + 2048)

__global__ __launch_bounds__(128, 3)
void attn_hmma(const __nv_bfloat16* __restrict__ Qh, const __nv_bfloat16* __restrict__ Ql,
               const __nv_bfloat16* __restrict__ Kh, const __nv_bfloat16* __restrict__ Kl,
               const __nv_bfloat16* __restrict__ Vh, const __nv_bfloat16* __restrict__ Vl,
               const int* __restrict__ mask,
               __nv_bfloat16* __restrict__ Ohi, __nv_bfloat16* __restrict__ Olo)
{
    extern __shared__ char sm[];
    const uint32_t sb = smem_u32(sm);
    float* msk_s = (float*)(sm + 49152);
    const int tid = threadIdx.x, w = tid >> 5, L = tid & 31;
    const int qt = blockIdx.x, hh = blockIdx.y, b = blockIdx.z;
    const size_t base = (size_t)b * SEQ * DMODEL + (size_t)hh * DH;

    {
        const __nv_bfloat16* qh = Qh + base + (size_t)(qt * 64) * DMODEL;
        const __nv_bfloat16* ql = Ql + base + (size_t)(qt * 64) * DMODEL;
        #pragma unroll
        for (int it = 0; it < 4; it++) {
            int u = tid + it * 128;
            int r = u >> 3, c = u & 7;
            uint32_t off = (uint32_t)(r * 128 + ((c ^ (r & 7)) << 4));
            *(uint4*)(sm + off)        = *(const uint4*)(qh + (size_t)r * DMODEL + c * 8);
            *(uint4*)(sm + 8192 + off) = *(const uint4*)(ql + (size_t)r * DMODEL + c * 8);
        }
        #pragma unroll
        for (int i = 0; i < 4; i++)
            msk_s[tid + i * 128] = (float)mask[b * SEQ + tid + i * 128];
    }

    float m0 = -1e30f, m1 = -1e30f, l0 = 0.f, l1 = 0.f;
    float o[8][4];
    #pragma unroll
    for (int f = 0; f < 8; f++)
        #pragma unroll
        for (int t = 0; t < 4; t++) o[f][t] = 0.f;

    for (int kt = 0; kt < SEQ / 64; kt++) {
        __syncthreads();
        {
            const size_t kb = base + (size_t)(kt * 64) * DMODEL;
            #pragma unroll
            for (int it = 0; it < 4; it++) {
                int u = tid + it * 128;
                int r = u >> 3, c = u & 7;
                uint32_t off = (uint32_t)(r * 128 + ((c ^ (r & 7)) << 4));
                size_t g = kb + (size_t)r * DMODEL + c * 8;
                *(uint4*)(sm + 16384 + off) = *(const uint4*)(Kh + g);
                *(uint4*)(sm + 24576 + off) = *(const uint4*)(Kl + g);
                *(uint4*)(sm + 32768 + off) = *(const uint4*)(Vh + g);
                *(uint4*)(sm + 40960 + off) = *(const uint4*)(Vl + g);
            }
        }
        __syncthreads();

        float s[8][4];
        #pragma unroll
        for (int f = 0; f < 8; f++)
            #pragma unroll
            for (int t = 0; t < 4; t++) s[f][t] = 0.f;

        #pragma unroll
        for (int ks = 0; ks < 4; ks++) {
            const int qrow = w * 16 + (L & 15);
            const uint32_t qoff = (uint32_t)(qrow * 128
                                  + (((ks * 2 + (L >> 4)) ^ (qrow & 7)) << 4));
            uint32_t qhf[4], qlf[4];
            ldsm4(qhf, sb + qoff);
            ldsm4(qlf, sb + 8192 + qoff);
            #pragma unroll
            for (int nj = 0; nj < 4; nj++) {
                const int krow = nj * 16 + (L & 7) + ((L >> 4) << 3);
                const uint32_t koff = (uint32_t)(krow * 128
                                      + (((ks * 2 + ((L >> 3) & 1)) ^ (krow & 7)) << 4));
                uint32_t khf[4], klf[4];
                ldsm4(khf, sb + 16384 + koff);
                ldsm4(klf, sb + 24576 + koff);
                mma16816(s[2*nj],   qhf, khf[0], khf[1]);
                mma16816(s[2*nj+1], qhf, khf[2], khf[3]);
                mma16816(s[2*nj],   qhf, klf[0], klf[1]);
                mma16816(s[2*nj+1], qhf, klf[2], klf[3]);
                mma16816(s[2*nj],   qlf, khf[0], khf[1]);
                mma16816(s[2*nj+1], qlf, khf[2], khf[3]);
            }
        }

        #pragma unroll
        for (int f = 0; f < 8; f++) {
            float mk0 = msk_s[kt * 64 + f * 8 + 2 * (L & 3)];
            float mk1 = msk_s[kt * 64 + f * 8 + 2 * (L & 3) + 1];
            if (mk0 == 0.f) { s[f][0] = -1e9f; s[f][2] = -1e9f; }
            if (mk1 == 0.f) { s[f][1] = -1e9f; s[f][3] = -1e9f; }
        }

        float mx0 = -1e30f, mx1 = -1e30f;
        #pragma unroll
        for (int f = 0; f < 8; f++) {
            mx0 = fmaxf(mx0, fmaxf(s[f][0], s[f][1]));
            mx1 = fmaxf(mx1, fmaxf(s[f][2], s[f][3]));
        }
        #pragma unroll
        for (int ofs = 1; ofs <= 2; ofs <<= 1) {
            mx0 = fmaxf(mx0, __shfl_xor_sync(0xffffffffu, mx0, ofs, 4));
            mx1 = fmaxf(mx1, __shfl_xor_sync(0xffffffffu, mx1, ofs, 4));
        }
        float mn0 = fmaxf(m0, mx0), mn1 = fmaxf(m1, mx1);
        float al0 = __expf(m0 - mn0), al1 = __expf(m1 - mn1);
        m0 = mn0; m1 = mn1;
        float sum0 = 0.f, sum1 = 0.f;
        #pragma unroll
        for (int f = 0; f < 8; f++) {
            s[f][0] = __expf(s[f][0] - mn0); sum0 += s[f][0];
            s[f][1] = __expf(s[f][1] - mn0); sum0 += s[f][1];
            s[f][2] = __expf(s[f][2] - mn1); sum1 += s[f][2];
            s[f][3] = __expf(s[f][3] - mn1); sum1 += s[f][3];
        }
        #pragma unroll
        for (int ofs = 1; ofs <= 2; ofs <<= 1) {
            sum0 += __shfl_xor_sync(0xffffffffu, sum0, ofs, 4);
            sum1 += __shfl_xor_sync(0xffffffffu, sum1, ofs, 4);
        }
        l0 = l0 * al0 + sum0;
        l1 = l1 * al1 + sum1;
        #pragma unroll
        for (int f = 0; f < 8; f++) {
            o[f][0] *= al0; o[f][1] *= al0; o[f][2] *= al1; o[f][3] *= al1;
        }

        #pragma unroll
        for (int s4 = 0; s4 < 4; s4++) {
            uint32_t ph[4], pl[4];
            {
                float p00 = s[2*s4][0],   p01 = s[2*s4][1];
                float p02 = s[2*s4][2],   p03 = s[2*s4][3];
                float p10 = s[2*s4+1][0], p11 = s[2*s4+1][1];
                float p12 = s[2*s4+1][2], p13 = s[2*s4+1][3];
                ph[0] = packbf(p00, p01); ph[1] = packbf(p02, p03);
                ph[2] = packbf(p10, p11); ph[3] = packbf(p12, p13);
                pl[0] = packbf(p00 - __bfloat162float(__float2bfloat16_rn(p00)),
                               p01 - __bfloat162float(__float2bfloat16_rn(p01)));
                pl[1] = packbf(p02 - __bfloat162float(__float2bfloat16_rn(p02)),
                               p03 - __bfloat162float(__float2bfloat16_rn(p03)));
                pl[2] = packbf(p10 - __bfloat162float(__float2bfloat16_rn(p10)),
                               p11 - __bfloat162float(__float2bfloat16_rn(p11)));
                pl[3] = packbf(p12 - __bfloat162float(__float2bfloat16_rn(p12)),
                               p13 - __bfloat162float(__float2bfloat16_rn(p13)));
            }
            #pragma unroll
            for (int dj = 0; dj < 4; dj++) {
                const int vrow = s4 * 16 + (L & 15);
                const uint32_t voff = (uint32_t)(vrow * 128
                                      + (((dj * 2 + (L >> 4)) ^ (vrow & 7)) << 4));
                uint32_t vhf[4], vlf[4];
                ldsm4t(vhf, sb + 32768 + voff);
                ldsm4t(vlf, sb + 40960 + voff);
                mma16816(o[2*dj],   ph, vhf[0], vhf[1]);
                mma16816(o[2*dj+1], ph, vhf[2], vhf[3]);
                mma16816(o[2*dj],   ph, vlf[0], vlf[1]);
                mma16816(o[2*dj+1], ph, vlf[2], vlf[3]);
                mma16816(o[2*dj],   pl, vhf[0], vhf[1]);
                mma16816(o[2*dj+1], pl, vhf[2], vhf[3]);
            }
        }
    }

    const float inv0 = 1.f / l0, inv1 = 1.f / l1;
    const int r0 = qt * 64 + w * 16 + (L >> 2);
    #pragma unroll
    for (int f = 0; f < 8; f++) {
        const int c = f * 8 + 2 * (L & 3);
        const size_t i0 = base + (size_t)r0 * DMODEL + c;
        const size_t i1 = base + (size_t)(r0 + 8) * DMODEL + c;
        float v0 = o[f][0] * inv0, v1 = o[f][1] * inv0;
        float v2 = o[f][2] * inv1, v3 = o[f][3] * inv1;
        float h0 = __bfloat162float(__float2bfloat16_rn(v0));
        float h1 = __bfloat162float(__float2bfloat16_rn(v1));
        float h2v = __bfloat162float(__float2bfloat16_rn(v2));
        float h3 = __bfloat162float(__float2bfloat16_rn(v3));
        *(uint32_t*)(Ohi + i0) = packbf(v0, v1);
        *(uint32_t*)(Olo + i0) = packbf(v0 - h0, v1 - h1);
        *(uint32_t*)(Ohi + i1) = packbf(v2, v3);
        *(uint32_t*)(Olo + i1) = packbf(v2 - h2v, v3 - h3);
    }
}

// ---------------- residual add + LayerNorm (float4, 192 threads/row) --------
__device__ __forceinline__ float blockReduceSum6(float val)
{
    __shared__ float red[6];
    __syncthreads();
    int lane = threadIdx.x & 31, wid = threadIdx.x >> 5;
    #pragma unroll
    for (int o = 16; o > 0; o >>= 1) val += __shfl_down_sync(0xffffffffu, val, o);
    if (lane == 0) red[wid] = val;
    __syncthreads();
    if (wid == 0) {
        val = (lane < 6) ? red[lane] : 0.f;
        #pragma unroll
        for (int o = 4; o > 0; o >>= 1) val += __shfl_down_sync(0xffffffffu, val, o);
        if (lane == 0) red[0] = val;
    }
    __syncthreads();
    return red[0];
}

__global__ __launch_bounds__(192)
void add_ln_kernel(const float* __restrict__ a, const float* __restrict__ res,
                   const float* __restrict__ g, const float* __restrict__ bt,
                   float* __restrict__ out,
                   __nv_bfloat16* __restrict__ ohi, __nv_bfloat16* __restrict__ olo)
{
    const int row = blockIdx.x;
    const int c4 = threadIdx.x * 4;
    const size_t rb = (size_t)row * DMODEL + c4;

    float4 av = *(const float4*)(a + rb);
    float4 rv = *(const float4*)(res + rb);
    float v0 = av.x + rv.x, v1 = av.y + rv.y, v2 = av.z + rv.z, v3 = av.w + rv.w;

    float sum = blockReduceSum6(v0 + v1 + v2 + v3);
    const float mu = sum * (1.f / DMODEL);
    float d0 = v0 - mu, d1 = v1 - mu, d2 = v2 - mu, d3 = v3 - mu;
    float s2 = blockReduceSum6(d0*d0 + d1*d1 + d2*d2 + d3*d3);
    const float rs = rsqrtf(s2 * (1.f / DMODEL) + 1e-12f);

    float4 gv = *(const float4*)(g + c4);
    float4 bv = *(const float4*)(bt + c4);
    float o0 = d0 * rs * gv.x + bv.x;
    float o1 = d1 * rs * gv.y + bv.y;
    float o2 = d2 * rs * gv.z + bv.z;
    float o3 = d3 * rs * gv.w + bv.w;
    float4 ov = { o0, o1, o2, o3 };
    *(float4*)(out + rb) = ov;
    if (ohi) {
        float h0 = __bfloat162float(__float2bfloat16_rn(o0));
        float h1 = __bfloat162float(__float2bfloat16_rn(o1));
        float h2 = __bfloat162float(__float2bfloat16_rn(o2));
        float h3 = __bfloat162float(__float2bfloat16_rn(o3));
        uint2 H  = { packbf(o0, o1), packbf(o2, o3) };
        uint2 Lo = { packbf(o0 - h0, o1 - h1), packbf(o2 - h2, o3 - h3) };
        *(uint2*)(ohi + rb) = H;
        *(uint2*)(olo + rb) = Lo;
    }
}

// ---------------- driver -----------------------------------------------------
extern "C" void kernel_launch(void* const* d_in, const int* in_sizes, int n_in,
                              void* d_out, int out_size)
{
    const float* x     = (const float*)d_in[0];
    const int*   amask = (const int*)  d_in[1];
    const float* Wq    = (const float*)d_in[2];
    const float* bq    = (const float*)d_in[3];
    const float* Wk    = (const float*)d_in[4];
    const float* bk    = (const float*)d_in[5];
    const float* Wv    = (const float*)d_in[6];
    const float* bv    = (const float*)d_in[7];
    const float* Wo    = (const float*)d_in[8];
    const float* bo    = (const float*)d_in[9];
    const float* ln1g  = (const float*)d_in[10];
    const float* ln1b  = (const float*)d_in[11];
    const float* W1    = (const float*)d_in[12];
    const float* b1    = (const float*)d_in[13];
    const float* W2    = (const float*)d_in[14];
    const float* b2    = (const float*)d_in[15];
    const float* ln2g  = (const float*)d_in[16];
    const float* ln2b  = (const float*)d_in[17];
    float* out = (float*)d_out;

    float *h, *h2, *tmp;
    __nv_bfloat16 *whi, *wlo, *ahi, *alo, *chi, *clo, *fhi, *flo;
    __nv_bfloat16 *qhi, *qlo, *khi, *klo, *vhi, *vlo;
    cudaGetSymbolAddress((void**)&h,   g_h);
    cudaGetSymbolAddress((void**)&h2,  g_h2);
    cudaGetSymbolAddress((void**)&tmp, g_tmp);
    cudaGetSymbolAddress((void**)&whi, g_whi);
    cudaGetSymbolAddress((void**)&wlo, g_wlo);
    cudaGetSymbolAddress((void**)&ahi, g_ahi);
    cudaGetSymbolAddress((void**)&alo, g_alo);
    cudaGetSymbolAddress((void**)&qhi, g_qhi);
    cudaGetSymbolAddress((void**)&qlo, g_qlo);
    cudaGetSymbolAddress((void**)&khi, g_khi);
    cudaGetSymbolAddress((void**)&klo, g_klo);
    cudaGetSymbolAddress((void**)&vhi, g_vhi);
    cudaGetSymbolAddress((void**)&vlo, g_vlo);
    cudaGetSymbolAddress((void**)&chi, g_chi);
    cudaGetSymbolAddress((void**)&clo, g_clo);
    cudaGetSymbolAddress((void**)&fhi, g_fhi);
    cudaGetSymbolAddress((void**)&flo, g_flo);

    cudaFuncSetAttribute(hmma_gemm<4>, cudaFuncAttributeMaxDynamicSharedMemorySize, GEMM_SMEM4);
    cudaFuncSetAttribute(hmma_gemm<2>, cudaFuncAttributeMaxDynamicSharedMemorySize, GEMM_SMEM2);
    cudaFuncSetAttribute(attn_hmma, cudaFuncAttributeMaxDynamicSharedMemorySize, ATT_SMEM);

    const int nDD4 = SZ_DD / 4;
    const int nDF4 = SZ_DF / 4;
    f2bf<<<nDD4/256, 256>>>((const float4*)Wq, (uint2*)(whi+OQ),  (uint2*)(wlo+OQ),  nDD4);
    f2bf<<<nDD4/256, 256>>>((const float4*)Wk, (uint2*)(whi+OKk), (uint2*)(wlo+OKk), nDD4);
    f2bf<<<nDD4/256, 256>>>((const float4*)Wv, (uint2*)(whi+OV),  (uint2*)(wlo+OV),  nDD4);
    f2bf<<<nDD4/256, 256>>>((const float4*)Wo, (uint2*)(whi+OO),  (uint2*)(wlo+OO),  nDD4);
    f2bf<<<nDF4/256, 256>>>((const float4*)W1, (uint2*)(whi+O1),  (uint2*)(wlo+O1),  nDF4);
    f2bf<<<nDF4/256, 256>>>((const float4*)W2, (uint2*)(whi+O2),  (uint2*)(wlo+O2),  nDF4);

    const int nAct4 = NTOK * DMODEL / 4;
    const dim3 gQKV(DMODEL / 128, NTOK / 128, 3);   // MT=4
    const dim3 gD2 (DMODEL / 128, NTOK / 64,  1);   // MT=2
    const dim3 gF  (FFD    / 128, NTOK / 128, 1);   // MT=4
    const dim3 gA(SEQ / 64, NH, BATCH);

    f2bf<<<nAct4/256, 256>>>((const float4*)x, (uint2*)ahi, (uint2*)alo, nAct4);

    for (int i = 0; i < NL; i++) {
        const float* cur = (i == 0) ? x : h;
        const size_t wdd = (size_t)i * DMODEL * DMODEL;
        const size_t wdf = (size_t)i * DMODEL * FFD;

        GemmParams pq = {};
        pq.job[0] = { whi+OQ+wdd,  wlo+OQ+wdd,  bq + i*DMODEL, 0, qhi, qlo, 0.125f, 0 };
        pq.job[1] = { whi+OKk+wdd, wlo+OKk+wdd, bk + i*DMODEL, 0, khi, klo, 1.f,    0 };
        pq.job[2] = { whi+OV+wdd,  wlo+OV+wdd,  bv + i*DMODEL, 0, vhi, vlo, 1.f,    0 };
        hmma_gemm<4><<<gQKV, 128, GEMM_SMEM4>>>(ahi, alo, pq, NTOK, DMODEL, DMODEL);

        attn_hmma<<<gA, 128, ATT_SMEM>>>(qhi, qlo, khi, klo, vhi, vlo, amask, chi, clo);

        GemmParams po = {};
        po.job[0] = { whi+OO+wdd, wlo+OO+wdd, bo + i*DMODEL, tmp, 0, 0, 1.f, 0 };
        hmma_gemm<2><<<gD2, 128, GEMM_SMEM2>>>(chi, clo, po, NTOK, DMODEL, DMODEL);

        add_ln_kernel<<<NTOK, 192>>>(tmp, cur, ln1g + i*DMODEL, ln1b + i*DMODEL,
                                     h2, ahi, alo);

        GemmParams p1 = {};
        p1.job[0] = { whi+O1+wdf, wlo+O1+wdf, b1 + i*FFD, 0, fhi, flo, 1.f, 1 };
        hmma_gemm<4><<<gF, 128, GEMM_SMEM4>>>(ahi, alo, p1, NTOK, FFD, DMODEL);

        GemmParams p2 = {};
        p2.job[0] = { whi+O2+wdf, wlo+O2+wdf, b2 + i*DMODEL, tmp, 0, 0, 1.f, 0 };
        hmma_gemm<2><<<gD2, 128, GEMM_SMEM2>>>(fhi, flo, p2, NTOK, DMODEL, FFD);

        float* dst = (i == NL - 1) ? out : h;
        add_ln_kernel<<<NTOK, 192>>>(tmp, h2, ln2g + i*DMODEL, ln2b + i*DMODEL,
                                     dst, (i < NL-1) ? ahi : 0, (i < NL-1) ? alo : 0);
    }
}